// round 3
// baseline (speedup 1.0000x reference)
#include <cuda_runtime.h>
#include <cuda_bf16.h>

// ---------------------------------------------------------------------------
// VQVAE forward. Encoder + VQ replicate XLA-CPU (Eigen) fp32 rounding order
// bit-for-bit so the argmin matches the reference; decoder is free-order fp32.
// ---------------------------------------------------------------------------

#define BATCH 32
#define HID   128
#define EDIM  64
#define KCODES 512

// scratch (device globals; no allocation allowed)
__device__ float g_h1[(size_t)BATCH * HID * 128 * 128];     // 268 MB
__device__ float g_z [(size_t)BATCH * EDIM * 64 * 64];      // 33.5 MB
__device__ float g_zq[(size_t)BATCH * EDIM * 64 * 64];      // 33.5 MB (z_q_st)
__device__ float g_d1[(size_t)BATCH * HID * 128 * 128];     // 268 MB
__device__ int   g_idx[BATCH * 4096];
__device__ float g_wT2[16 * 128 * 64];                      // conv2 w: [tap][ci][co]
__device__ float g_wr1[4 * 64 * 128 * 4];                   // parity-major dec_w1
__device__ float g_wr2[4 * 128 * 3 * 4];                    // parity-major dec_w2
__device__ float g_cn[KCODES];                              // ||code||^2 (ref rounding)

// ---------------------------------------------------------------------------
// prep: codebook norms (separate mul+add, sequential ascending — XLA reduce),
// conv2 weight transpose to [tap][ci][co], deconv weight parity rearrangement.
// ---------------------------------------------------------------------------
__global__ void prep_k(const float* __restrict__ cb,
                       const float* __restrict__ ew2,
                       const float* __restrict__ dw1,
                       const float* __restrict__ dw2) {
    int t = blockIdx.x * blockDim.x + threadIdx.x;
    int stride = gridDim.x * blockDim.x;
    if (t < KCODES) {
        float s = 0.f;
        for (int d = 0; d < EDIM; d++) {
            float v = cb[t * EDIM + d];
            s = __fadd_rn(s, __fmul_rn(v, v));
        }
        g_cn[t] = s;
    }
    // conv2 weights: g_wT2[tap*8192 + ci*64 + co] = ew2[co*2048 + ci*16 + tap]
    for (int e = t; e < 16 * 128 * 64; e += stride) {
        int tap = e >> 13;
        int ci  = (e >> 6) & 127;
        int co  = e & 63;
        g_wT2[e] = ew2[(size_t)co * 2048 + ci * 16 + tap];
    }
    // wr1: 4 * 64 * 128 entries (p, ci, co), 4 taps each
    for (int e = t; e < 4 * 64 * 128; e += stride) {
        int p  = e >> 13;
        int ci = (e >> 7) & 63;
        int co = e & 127;
        int ph = p >> 1, pw = p & 1;
        const float* src = dw1 + ((size_t)co * 64 + ci) * 16;
        float* dst = g_wr1 + (size_t)e * 4;
        dst[0] = src[ ph      * 4 +  pw     ];
        dst[1] = src[ ph      * 4 + (pw + 2)];
        dst[2] = src[(ph + 2) * 4 +  pw     ];
        dst[3] = src[(ph + 2) * 4 + (pw + 2)];
    }
    // wr2: 4 * 128 * 3
    for (int e = t; e < 4 * 128 * 3; e += stride) {
        int p  = e / 384;
        int rem = e % 384;
        int ci = rem / 3;
        int co = rem % 3;
        int ph = p >> 1, pw = p & 1;
        const float* src = dw2 + ((size_t)co * 128 + ci) * 16;
        float* dst = g_wr2 + (size_t)e * 4;
        dst[0] = src[ ph      * 4 +  pw     ];
        dst[1] = src[ ph      * 4 + (pw + 2)];
        dst[2] = src[(ph + 2) * 4 +  pw     ];
        dst[3] = src[(ph + 2) * 4 + (pw + 2)];
    }
}

// ---------------------------------------------------------------------------
// conv1: x[32,3,256,256] -> relu -> h1[32,128,128,128], k=4 s=2 p=1.
// Sequential FMA chain in k-order (kh,kw) row-major outer, ci fastest.
// Bias added after (separate rounding), then relu.
// ---------------------------------------------------------------------------
__global__ __launch_bounds__(256) void conv1_k(const float* __restrict__ x,
                                               const float* __restrict__ w,
                                               const float* __restrict__ bias) {
    __shared__ float sW2[128 * 48];   // [co][tap*3+ci]
    __shared__ float sX[3 * 34 * 34];
    int b = blockIdx.z, oht = blockIdx.y, owt = blockIdx.x;
    int t = threadIdx.x;
    for (int i = t; i < 6144; i += 256) {
        int co = i / 48, r = i - co * 48;
        int tap = r / 3, ci = r - tap * 3;
        sW2[i] = w[co * 48 + ci * 16 + tap];
    }
    int ih0 = oht * 32 - 1, iw0 = owt * 32 - 1;
    const float* xb = x + (size_t)b * 3 * 256 * 256;
    for (int i = t; i < 3 * 1156; i += 256) {
        int ci = i / 1156, r = (i % 1156) / 34, c = i % 34;
        int ih = ih0 + r, iw = iw0 + c;
        sX[i] = ((unsigned)ih < 256u && (unsigned)iw < 256u)
                ? xb[((size_t)ci * 256 + ih) * 256 + iw] : 0.f;
    }
    __syncthreads();
    int oh_l = t >> 4, ow_l = t & 15;
    float xw[48];
    #pragma unroll
    for (int kh = 0; kh < 4; kh++)
        #pragma unroll
        for (int kw = 0; kw < 4; kw++)
            #pragma unroll
            for (int ci = 0; ci < 3; ci++)
                xw[(kh * 4 + kw) * 3 + ci] =
                    sX[ci * 1156 + (2 * oh_l + kh) * 34 + (2 * ow_l + kw)];
    int oh = oht * 16 + oh_l, ow = owt * 16 + ow_l;
    size_t obase = (size_t)b * 2097152 + (size_t)oh * 128 + ow;
    #pragma unroll 4
    for (int co = 0; co < 128; co++) {
        float acc = 0.f;
        const float4* w4 = (const float4*)(sW2 + co * 48);
        #pragma unroll
        for (int q = 0; q < 12; q++) {
            float4 v = w4[q];
            acc = fmaf(xw[q * 4 + 0], v.x, acc);
            acc = fmaf(xw[q * 4 + 1], v.y, acc);
            acc = fmaf(xw[q * 4 + 2], v.z, acc);
            acc = fmaf(xw[q * 4 + 3], v.w, acc);
        }
        float val = __fadd_rn(acc, __ldg(bias + co));
        g_h1[obase + (size_t)co * 16384] = fmaxf(val, 0.f);
    }
}

// ---------------------------------------------------------------------------
// conv2: h1 -> z[32,64,64,64], k=4 s=2 p=1. Sequential FMA chain per output
// in k-order: taps (kh,kw) outer, ci 0..127 inner. Full 128-ci 18x18 input
// patch resident in dynamic smem; weights staged per tap. Bias added after.
// Block: 8x8 spatial x 4 threads (16 co each) = 256 threads.
// ---------------------------------------------------------------------------
extern __shared__ float smem2[];
__global__ __launch_bounds__(256) void conv2_k(const float* __restrict__ bias) {
    float* sX = smem2;              // 128 * 324
    float* sW = smem2 + 41472;      // 128 * 64
    int b = blockIdx.z, oht = blockIdx.y, owt = blockIdx.x;
    int t = threadIdx.x;
    int p = t >> 2, tq = t & 3;
    int r = p >> 3, c = p & 7;
    int ih0 = oht * 16 - 1, iw0 = owt * 16 - 1;
    const float* h1b = g_h1 + (size_t)b * 2097152;
    for (int i = t; i < 128 * 324; i += 256) {
        int ci = i / 324, rem = i % 324;
        int lr = rem / 18, lc = rem % 18;
        int ih = ih0 + lr, iw = iw0 + lc;
        sX[i] = ((unsigned)ih < 128u && (unsigned)iw < 128u)
                ? h1b[(size_t)ci * 16384 + ih * 128 + iw] : 0.f;
    }
    float acc[16];
    #pragma unroll
    for (int j = 0; j < 16; j++) acc[j] = 0.f;
    for (int tap = 0; tap < 16; tap++) {
        __syncthreads();
        const float4* src = (const float4*)(g_wT2 + tap * 8192);
        for (int i = t; i < 2048; i += 256)
            ((float4*)sW)[i] = src[i];
        __syncthreads();
        int kh = tap >> 2, kw = tap & 3;
        int xi = (2 * r + kh) * 18 + (2 * c + kw);
        #pragma unroll 2
        for (int ci = 0; ci < 128; ci++) {
            float xv = sX[ci * 324 + xi];
            const float4* wp = (const float4*)(sW + ci * 64 + tq * 16);
            float4 w0 = wp[0], w1 = wp[1], w2 = wp[2], w3 = wp[3];
            acc[0]  = fmaf(xv, w0.x, acc[0]);
            acc[1]  = fmaf(xv, w0.y, acc[1]);
            acc[2]  = fmaf(xv, w0.z, acc[2]);
            acc[3]  = fmaf(xv, w0.w, acc[3]);
            acc[4]  = fmaf(xv, w1.x, acc[4]);
            acc[5]  = fmaf(xv, w1.y, acc[5]);
            acc[6]  = fmaf(xv, w1.z, acc[6]);
            acc[7]  = fmaf(xv, w1.w, acc[7]);
            acc[8]  = fmaf(xv, w2.x, acc[8]);
            acc[9]  = fmaf(xv, w2.y, acc[9]);
            acc[10] = fmaf(xv, w2.z, acc[10]);
            acc[11] = fmaf(xv, w2.w, acc[11]);
            acc[12] = fmaf(xv, w3.x, acc[12]);
            acc[13] = fmaf(xv, w3.y, acc[13]);
            acc[14] = fmaf(xv, w3.z, acc[14]);
            acc[15] = fmaf(xv, w3.w, acc[15]);
        }
    }
    int oh = oht * 8 + r, ow = owt * 8 + c;
    size_t ob = (size_t)b * 262144 + (size_t)oh * 64 + ow;
    #pragma unroll
    for (int j = 0; j < 16; j++) {
        int co = tq * 16 + j;
        g_z[ob + (size_t)co * 4096] = __fadd_rn(acc[j], __ldg(bias + co));
    }
}

// ---------------------------------------------------------------------------
// VQ assign. Vector v: z[b, c, h, 0:64] (contiguous row, varying w).
// Replicates reference arithmetic:
//   zz = sequential fl(s + fl(z*z)), dot = sequential fmaf chain ascending e,
//   d2 = fl(fl(zz - 2*dot) + cn), ascending code scan, strict < (first min).
// ---------------------------------------------------------------------------
__global__ __launch_bounds__(256) void vq_k(const float* __restrict__ cb) {
    __shared__ float sC[128 * 64];
    __shared__ float sN[128];
    int v = blockIdx.x * 256 + threadIdx.x;
    float z[64];
    const float4* zp = (const float4*)(g_z + (size_t)v * 64);
    #pragma unroll
    for (int q = 0; q < 16; q++) {
        float4 f = zp[q];
        z[q * 4 + 0] = f.x; z[q * 4 + 1] = f.y;
        z[q * 4 + 2] = f.z; z[q * 4 + 3] = f.w;
    }
    float zz = 0.f;
    #pragma unroll
    for (int e = 0; e < 64; e++)
        zz = __fadd_rn(zz, __fmul_rn(z[e], z[e]));
    float best = 3.4e38f;
    int bi = 0;
    for (int ch = 0; ch < 4; ch++) {
        __syncthreads();
        const float4* src = (const float4*)cb + (size_t)ch * 2048;
        for (int i = threadIdx.x; i < 2048; i += 256)
            ((float4*)sC)[i] = src[i];
        if (threadIdx.x < 128) sN[threadIdx.x] = g_cn[ch * 128 + threadIdx.x];
        __syncthreads();
        for (int kk = 0; kk < 128; kk += 2) {
            const float4* c0 = (const float4*)(sC + kk * 64);
            const float4* c1 = (const float4*)(sC + kk * 64 + 64);
            float s0 = 0.f, s1 = 0.f;
            #pragma unroll
            for (int q = 0; q < 16; q++) {
                float4 a = c0[q], bq = c1[q];
                s0 = fmaf(z[q*4+0], a.x, s0);
                s0 = fmaf(z[q*4+1], a.y, s0);
                s0 = fmaf(z[q*4+2], a.z, s0);
                s0 = fmaf(z[q*4+3], a.w, s0);
                s1 = fmaf(z[q*4+0], bq.x, s1);
                s1 = fmaf(z[q*4+1], bq.y, s1);
                s1 = fmaf(z[q*4+2], bq.z, s1);
                s1 = fmaf(z[q*4+3], bq.w, s1);
            }
            float d0 = __fadd_rn(__fadd_rn(zz, -2.f * s0), sN[kk]);
            float d1 = __fadd_rn(__fadd_rn(zz, -2.f * s1), sN[kk + 1]);
            if (d0 < best) { best = d0; bi = ch * 128 + kk; }
            if (d1 < best) { best = d1; bi = ch * 128 + kk + 1; }
        }
    }
    g_idx[v] = bi;
}

// ---------------------------------------------------------------------------
// z_q scatter + straight-through: st[b][C][n] = fl(z + fl(cb[idx[n]][C] - z)).
// n = H*64+W; same linear offset in z and st.
// ---------------------------------------------------------------------------
__global__ __launch_bounds__(256) void zq_k(const float* __restrict__ cb) {
    int v = blockIdx.x * 256 + threadIdx.x;
    int b = v >> 12, n = v & 4095;
    int id = g_idx[v];
    const float* c = cb + (size_t)id * 64;
    size_t base = (size_t)b * 262144 + n;
    #pragma unroll 8
    for (int ch = 0; ch < 64; ch++) {
        size_t off = base + (size_t)ch * 4096;
        float zv = g_z[off];
        float q  = __ldg(c + ch);
        g_zq[off] = __fadd_rn(zv, __fadd_rn(q, -zv));
    }
}

// ---------------------------------------------------------------------------
// deconv1: zq_st[32,64,64,64] -> relu -> d1[32,128,128,128]
// parity-decomposed transposed conv; free rounding order (decoder only).
// ---------------------------------------------------------------------------
__global__ __launch_bounds__(256, 2) void deconv1_k(const float* __restrict__ bias) {
    __shared__ float sX[64 * 100];       // 10x10 patch per ci, all 64 ci
    __shared__ float sW[4 * 4 * 64 * 4]; // [p][ci4][co64][4]
    __shared__ float sB[64];
    int bz = blockIdx.z;
    int b = bz >> 1, half = bz & 1;
    int oht = blockIdx.y, owt = blockIdx.x;
    int t = threadIdx.x;
    if (t < 64) sB[t] = bias[half * 64 + t];
    int r0 = oht * 8 - 1, c0 = owt * 8 - 1;
    const float* zq = g_zq + (size_t)b * 262144;
    for (int i = t; i < 6400; i += 256) {
        int ci = i / 100, rr = (i % 100) / 10, cc = i % 10;
        int ih = r0 + rr, iw = c0 + cc;
        sX[i] = ((unsigned)ih < 64u && (unsigned)iw < 64u)
                ? zq[(size_t)ci * 4096 + ih * 64 + iw] : 0.f;
    }
    __syncthreads();
    int oh_l = t >> 4, ow_l = t & 15;
    int ph = oh_l & 1, pw = ow_l & 1, p = ph * 2 + pw;
    int xr = (oh_l >> 1) + ph;
    int xc = (ow_l >> 1) + pw;
    float acc[64];
    #pragma unroll
    for (int co = 0; co < 64; co++) acc[co] = sB[co];
    for (int cc4 = 0; cc4 < 16; cc4++) {
        __syncthreads();
        for (int i = t; i < 1024; i += 256) {
            int pp = i >> 8, rem = i & 255;
            int c4 = rem >> 6, co = rem & 63;
            ((float4*)sW)[i] =
                ((const float4*)g_wr1)[((size_t)pp * 64 + (cc4 * 4 + c4)) * 128 + half * 64 + co];
        }
        __syncthreads();
        #pragma unroll
        for (int c4 = 0; c4 < 4; c4++) {
            int base = (cc4 * 4 + c4) * 100;
            float x00 = sX[base + xr * 10 + xc];
            float x01 = sX[base + xr * 10 + xc + 1];
            float x10 = sX[base + (xr + 1) * 10 + xc];
            float x11 = sX[base + (xr + 1) * 10 + xc + 1];
            const float4* wrow = (const float4*)sW + (p * 4 + c4) * 64;
            #pragma unroll
            for (int co = 0; co < 64; co++) {
                float4 wv = wrow[co];
                float s = acc[co];
                s = fmaf(x00, wv.x, s);
                s = fmaf(x01, wv.y, s);
                s = fmaf(x10, wv.z, s);
                s = fmaf(x11, wv.w, s);
                acc[co] = s;
            }
        }
    }
    int oh = oht * 16 + oh_l, ow = owt * 16 + ow_l;
    size_t obase = (size_t)b * 2097152 + (size_t)(half * 64) * 16384
                 + (size_t)oh * 128 + ow;
    #pragma unroll
    for (int co = 0; co < 64; co++)
        g_d1[obase + (size_t)co * 16384] = fmaxf(acc[co], 0.f);
}

// ---------------------------------------------------------------------------
// deconv2: d1[32,128,128,128] -> out[32,3,256,256] (no relu), same structure.
// ---------------------------------------------------------------------------
__global__ __launch_bounds__(256) void deconv2_k(const float* __restrict__ bias,
                                                 float* __restrict__ out) {
    __shared__ float sX[32 * 100];
    __shared__ float sW[4 * 32 * 3 * 4];
    int b = blockIdx.z, oht = blockIdx.y, owt = blockIdx.x;
    int t = threadIdx.x;
    int r0 = oht * 8 - 1, c0 = owt * 8 - 1;
    int oh_l = t >> 4, ow_l = t & 15;
    int ph = oh_l & 1, pw = ow_l & 1, p = ph * 2 + pw;
    int xr = (oh_l >> 1) + ph;
    int xc = (ow_l >> 1) + pw;
    const float* d1b = g_d1 + (size_t)b * 2097152;
    float a0 = 0.f, a1 = 0.f, a2 = 0.f;
    for (int chn = 0; chn < 4; chn++) {
        __syncthreads();
        for (int i = t; i < 3200; i += 256) {
            int ci = i / 100, rr = (i % 100) / 10, cc = i % 10;
            int ih = r0 + rr, iw = c0 + cc;
            sX[i] = ((unsigned)ih < 128u && (unsigned)iw < 128u)
                    ? d1b[(size_t)(chn * 32 + ci) * 16384 + ih * 128 + iw] : 0.f;
        }
        for (int i = t; i < 384; i += 256) {
            int pp = i / 96, rem = i % 96;
            int ci = rem / 3, co = rem % 3;
            ((float4*)sW)[i] =
                ((const float4*)g_wr2)[((size_t)pp * 128 + chn * 32 + ci) * 3 + co];
        }
        __syncthreads();
        #pragma unroll 4
        for (int ci = 0; ci < 32; ci++) {
            int base = ci * 100;
            float x00 = sX[base + xr * 10 + xc];
            float x01 = sX[base + xr * 10 + xc + 1];
            float x10 = sX[base + (xr + 1) * 10 + xc];
            float x11 = sX[base + (xr + 1) * 10 + xc + 1];
            const float4* wr = (const float4*)sW + (p * 32 + ci) * 3;
            float4 w0 = wr[0], w1 = wr[1], w2 = wr[2];
            a0 = fmaf(x00, w0.x, a0); a0 = fmaf(x01, w0.y, a0);
            a0 = fmaf(x10, w0.z, a0); a0 = fmaf(x11, w0.w, a0);
            a1 = fmaf(x00, w1.x, a1); a1 = fmaf(x01, w1.y, a1);
            a1 = fmaf(x10, w1.z, a1); a1 = fmaf(x11, w1.w, a1);
            a2 = fmaf(x00, w2.x, a2); a2 = fmaf(x01, w2.y, a2);
            a2 = fmaf(x10, w2.z, a2); a2 = fmaf(x11, w2.w, a2);
        }
    }
    int oh = oht * 16 + oh_l, ow = owt * 16 + ow_l;
    size_t obase = (size_t)b * 3 * 65536 + (size_t)oh * 256 + ow;
    out[obase]              = a0 + __ldg(bias + 0);
    out[obase + 65536]      = a1 + __ldg(bias + 1);
    out[obase + 2 * 65536]  = a2 + __ldg(bias + 2);
}

// ---------------------------------------------------------------------------
extern "C" void kernel_launch(void* const* d_in, const int* in_sizes, int n_in,
                              void* d_out, int out_size) {
    const float* x      = (const float*)d_in[0];
    const float* enc_w1 = (const float*)d_in[1];
    const float* enc_b1 = (const float*)d_in[2];
    const float* enc_w2 = (const float*)d_in[3];
    const float* enc_b2 = (const float*)d_in[4];
    const float* dec_w1 = (const float*)d_in[5];
    const float* dec_b1 = (const float*)d_in[6];
    const float* dec_w2 = (const float*)d_in[7];
    const float* dec_b2 = (const float*)d_in[8];
    const float* cb     = (const float*)d_in[9];
    float* out = (float*)d_out;

    static int smem_set = 0;
    if (!smem_set) {
        cudaFuncSetAttribute(conv2_k, cudaFuncAttributeMaxDynamicSharedMemorySize,
                             (41472 + 8192) * 4);
        smem_set = 1;
    }

    prep_k<<<64, 256>>>(cb, enc_w2, dec_w1, dec_w2);
    conv1_k<<<dim3(8, 8, BATCH), 256>>>(x, enc_w1, enc_b1);
    conv2_k<<<dim3(8, 8, BATCH), 256, (41472 + 8192) * 4>>>(enc_b2);
    vq_k<<<512, 256>>>(cb);
    zq_k<<<512, 256>>>(cb);
    deconv1_k<<<dim3(8, 8, BATCH * 2), 256>>>(dec_b1);
    deconv2_k<<<dim3(16, 16, BATCH), 256>>>(dec_b2, out);
}

// round 4
// speedup vs baseline: 1.4850x; 1.4850x over previous
#include <cuda_runtime.h>
#include <cuda_bf16.h>

// ---------------------------------------------------------------------------
// VQVAE forward. Encoder + VQ replicate XLA-CPU (Eigen) fp32 rounding order
// bit-for-bit so the argmin matches the reference; decoder is free-order fp32.
// ---------------------------------------------------------------------------

#define BATCH 32
#define HID   128
#define EDIM  64
#define KCODES 512

// scratch (device globals; no allocation allowed)
__device__ float g_h1[(size_t)BATCH * HID * 128 * 128];     // 268 MB
__device__ float g_z [(size_t)BATCH * EDIM * 64 * 64];      // 33.5 MB
__device__ float g_zq[(size_t)BATCH * EDIM * 64 * 64];      // 33.5 MB (z_q_st)
__device__ float g_d1[(size_t)BATCH * HID * 128 * 128];     // 268 MB
__device__ int   g_idx[BATCH * 4096];
__device__ float g_wT2[16 * 128 * 64];                      // conv2 w: [tap][ci][co]
__device__ float g_wr1[4 * 64 * 128 * 4];                   // parity-major dec_w1
__device__ float g_wr2[4 * 128 * 3 * 4];                    // parity-major dec_w2
__device__ float g_cn[KCODES];                              // ||code||^2 (ref rounding)

// ---------------------------------------------------------------------------
// prep: codebook norms (separate mul+add, sequential ascending — XLA reduce),
// conv2 weight transpose to [tap][ci][co], deconv weight parity rearrangement.
// ---------------------------------------------------------------------------
__global__ void prep_k(const float* __restrict__ cb,
                       const float* __restrict__ ew2,
                       const float* __restrict__ dw1,
                       const float* __restrict__ dw2) {
    int t = blockIdx.x * blockDim.x + threadIdx.x;
    int stride = gridDim.x * blockDim.x;
    if (t < KCODES) {
        float s = 0.f;
        for (int d = 0; d < EDIM; d++) {
            float v = cb[t * EDIM + d];
            s = __fadd_rn(s, __fmul_rn(v, v));
        }
        g_cn[t] = s;
    }
    // conv2 weights: g_wT2[tap*8192 + ci*64 + co] = ew2[co*2048 + ci*16 + tap]
    for (int e = t; e < 16 * 128 * 64; e += stride) {
        int tap = e >> 13;
        int ci  = (e >> 6) & 127;
        int co  = e & 63;
        g_wT2[e] = ew2[(size_t)co * 2048 + ci * 16 + tap];
    }
    // wr1: 4 * 64 * 128 entries (p, ci, co), 4 taps each
    for (int e = t; e < 4 * 64 * 128; e += stride) {
        int p  = e >> 13;
        int ci = (e >> 7) & 63;
        int co = e & 127;
        int ph = p >> 1, pw = p & 1;
        const float* src = dw1 + ((size_t)co * 64 + ci) * 16;
        float* dst = g_wr1 + (size_t)e * 4;
        dst[0] = src[ ph      * 4 +  pw     ];
        dst[1] = src[ ph      * 4 + (pw + 2)];
        dst[2] = src[(ph + 2) * 4 +  pw     ];
        dst[3] = src[(ph + 2) * 4 + (pw + 2)];
    }
    // wr2: 4 * 128 * 3
    for (int e = t; e < 4 * 128 * 3; e += stride) {
        int p  = e / 384;
        int rem = e % 384;
        int ci = rem / 3;
        int co = rem % 3;
        int ph = p >> 1, pw = p & 1;
        const float* src = dw2 + ((size_t)co * 128 + ci) * 16;
        float* dst = g_wr2 + (size_t)e * 4;
        dst[0] = src[ ph      * 4 +  pw     ];
        dst[1] = src[ ph      * 4 + (pw + 2)];
        dst[2] = src[(ph + 2) * 4 +  pw     ];
        dst[3] = src[(ph + 2) * 4 + (pw + 2)];
    }
}

// ---------------------------------------------------------------------------
// conv1: x[32,3,256,256] -> relu -> h1[32,128,128,128], k=4 s=2 p=1.
// Sequential FMA chain in k-order (kh,kw) row-major outer, ci fastest.
// Bias added after (separate rounding), then relu.
// ---------------------------------------------------------------------------
__global__ __launch_bounds__(256) void conv1_k(const float* __restrict__ x,
                                               const float* __restrict__ w,
                                               const float* __restrict__ bias) {
    __shared__ float sW2[128 * 48];   // [co][tap*3+ci]
    __shared__ float sX[3 * 34 * 34];
    int b = blockIdx.z, oht = blockIdx.y, owt = blockIdx.x;
    int t = threadIdx.x;
    for (int i = t; i < 6144; i += 256) {
        int co = i / 48, r = i - co * 48;
        int tap = r / 3, ci = r - tap * 3;
        sW2[i] = w[co * 48 + ci * 16 + tap];
    }
    int ih0 = oht * 32 - 1, iw0 = owt * 32 - 1;
    const float* xb = x + (size_t)b * 3 * 256 * 256;
    for (int i = t; i < 3 * 1156; i += 256) {
        int ci = i / 1156, r = (i % 1156) / 34, c = i % 34;
        int ih = ih0 + r, iw = iw0 + c;
        sX[i] = ((unsigned)ih < 256u && (unsigned)iw < 256u)
                ? xb[((size_t)ci * 256 + ih) * 256 + iw] : 0.f;
    }
    __syncthreads();
    int oh_l = t >> 4, ow_l = t & 15;
    float xw[48];
    #pragma unroll
    for (int kh = 0; kh < 4; kh++)
        #pragma unroll
        for (int kw = 0; kw < 4; kw++)
            #pragma unroll
            for (int ci = 0; ci < 3; ci++)
                xw[(kh * 4 + kw) * 3 + ci] =
                    sX[ci * 1156 + (2 * oh_l + kh) * 34 + (2 * ow_l + kw)];
    int oh = oht * 16 + oh_l, ow = owt * 16 + ow_l;
    size_t obase = (size_t)b * 2097152 + (size_t)oh * 128 + ow;
    #pragma unroll 4
    for (int co = 0; co < 128; co++) {
        float acc = 0.f;
        const float4* w4 = (const float4*)(sW2 + co * 48);
        #pragma unroll
        for (int q = 0; q < 12; q++) {
            float4 v = w4[q];
            acc = fmaf(xw[q * 4 + 0], v.x, acc);
            acc = fmaf(xw[q * 4 + 1], v.y, acc);
            acc = fmaf(xw[q * 4 + 2], v.z, acc);
            acc = fmaf(xw[q * 4 + 3], v.w, acc);
        }
        float val = __fadd_rn(acc, __ldg(bias + co));
        g_h1[obase + (size_t)co * 16384] = fmaxf(val, 0.f);
    }
}

// ---------------------------------------------------------------------------
// conv2 v2: h1 -> z[32,64,64,64], k=4 s=2 p=1. Per-output chain UNCHANGED:
// taps (kh,kw) row-major outer, ci 0..127 inner, single fmaf chain, bias after.
// x read via __ldg (L2-resident per-image), per-tap weights streamed in smem.
// Thread = 2 horizontal outputs x 16 co; block = 8x16 outputs; 32 warps/SM.
// ---------------------------------------------------------------------------
__global__ __launch_bounds__(256) void conv2_k(const float* __restrict__ bias) {
    __shared__ float sW[8192];                 // [ci][co] for current tap, 32 KB
    int b = blockIdx.z, oht = blockIdx.y, owt = blockIdx.x;   // grid (4, 8, B)
    int t = threadIdx.x;
    int tq = t & 3;                  // co group: co = tq*16 + j
    int s  = t >> 2;                 // 0..63
    int row = s >> 3;                // 0..7
    int cp  = s & 7;                 // 0..7
    int oh  = oht * 8 + row;
    int ow0 = owt * 16 + cp * 2;
    const float* h1b = g_h1 + (size_t)b * 2097152;
    float accA[16], accB[16];
    #pragma unroll
    for (int j = 0; j < 16; j++) { accA[j] = 0.f; accB[j] = 0.f; }
    for (int tap = 0; tap < 16; tap++) {
        __syncthreads();
        {
            const float4* src = (const float4*)(g_wT2 + tap * 8192);
            float4* dst = (float4*)sW;
            #pragma unroll
            for (int i = 0; i < 8; i++) dst[t + 256 * i] = src[t + 256 * i];
        }
        __syncthreads();
        int kh = tap >> 2, kw = tap & 3;
        int ih  = 2 * oh + kh - 1;
        int iw0 = 2 * ow0 + kw - 1;
        bool p0 = ((unsigned)ih < 128u) && ((unsigned)iw0 < 128u);
        bool p1 = ((unsigned)ih < 128u) && ((unsigned)(iw0 + 2) < 128u);
        const float* xp = h1b + (size_t)ih * 128 + iw0;
        const float* wp = sW + tq * 16;
        #pragma unroll 2
        for (int ci = 0; ci < 128; ci++) {
            float x0 = p0 ? __ldg(xp + (size_t)ci * 16384) : 0.f;
            float x1 = p1 ? __ldg(xp + (size_t)ci * 16384 + 2) : 0.f;
            const float4* w4 = (const float4*)(wp + ci * 64);
            float4 w0 = w4[0], w1 = w4[1], w2 = w4[2], w3 = w4[3];
            accA[0]  = fmaf(x0, w0.x, accA[0]);  accB[0]  = fmaf(x1, w0.x, accB[0]);
            accA[1]  = fmaf(x0, w0.y, accA[1]);  accB[1]  = fmaf(x1, w0.y, accB[1]);
            accA[2]  = fmaf(x0, w0.z, accA[2]);  accB[2]  = fmaf(x1, w0.z, accB[2]);
            accA[3]  = fmaf(x0, w0.w, accA[3]);  accB[3]  = fmaf(x1, w0.w, accB[3]);
            accA[4]  = fmaf(x0, w1.x, accA[4]);  accB[4]  = fmaf(x1, w1.x, accB[4]);
            accA[5]  = fmaf(x0, w1.y, accA[5]);  accB[5]  = fmaf(x1, w1.y, accB[5]);
            accA[6]  = fmaf(x0, w1.z, accA[6]);  accB[6]  = fmaf(x1, w1.z, accB[6]);
            accA[7]  = fmaf(x0, w1.w, accA[7]);  accB[7]  = fmaf(x1, w1.w, accB[7]);
            accA[8]  = fmaf(x0, w2.x, accA[8]);  accB[8]  = fmaf(x1, w2.x, accB[8]);
            accA[9]  = fmaf(x0, w2.y, accA[9]);  accB[9]  = fmaf(x1, w2.y, accB[9]);
            accA[10] = fmaf(x0, w2.z, accA[10]); accB[10] = fmaf(x1, w2.z, accB[10]);
            accA[11] = fmaf(x0, w2.w, accA[11]); accB[11] = fmaf(x1, w2.w, accB[11]);
            accA[12] = fmaf(x0, w3.x, accA[12]); accB[12] = fmaf(x1, w3.x, accB[12]);
            accA[13] = fmaf(x0, w3.y, accA[13]); accB[13] = fmaf(x1, w3.y, accB[13]);
            accA[14] = fmaf(x0, w3.z, accA[14]); accB[14] = fmaf(x1, w3.z, accB[14]);
            accA[15] = fmaf(x0, w3.w, accA[15]); accB[15] = fmaf(x1, w3.w, accB[15]);
        }
    }
    size_t ob = (size_t)b * 262144 + (size_t)oh * 64 + ow0;
    #pragma unroll
    for (int j = 0; j < 16; j++) {
        int co = tq * 16 + j;
        float bv = __ldg(bias + co);
        g_z[ob + (size_t)co * 4096]     = __fadd_rn(accA[j], bv);
        g_z[ob + (size_t)co * 4096 + 1] = __fadd_rn(accB[j], bv);
    }
}

// ---------------------------------------------------------------------------
// VQ assign. Reference arithmetic preserved:
//   zz = sequential fl(s + fl(z*z)); dot = single ascending fmaf chain;
//   d2 = fl(fl(zz - 2*dot) + cn); ascending scan, strict < (first min).
// 4 codes per iteration for ILP (4 independent dot chains).
// ---------------------------------------------------------------------------
__global__ __launch_bounds__(256) void vq_k(const float* __restrict__ cb) {
    __shared__ float sC[128 * 64];
    __shared__ float sN[128];
    int v = blockIdx.x * 256 + threadIdx.x;
    float z[64];
    const float4* zp = (const float4*)(g_z + (size_t)v * 64);
    #pragma unroll
    for (int q = 0; q < 16; q++) {
        float4 f = zp[q];
        z[q * 4 + 0] = f.x; z[q * 4 + 1] = f.y;
        z[q * 4 + 2] = f.z; z[q * 4 + 3] = f.w;
    }
    float zz = 0.f;
    #pragma unroll
    for (int e = 0; e < 64; e++)
        zz = __fadd_rn(zz, __fmul_rn(z[e], z[e]));
    float best = 3.4e38f;
    int bi = 0;
    for (int ch = 0; ch < 4; ch++) {
        __syncthreads();
        const float4* src = (const float4*)cb + (size_t)ch * 2048;
        for (int i = threadIdx.x; i < 2048; i += 256)
            ((float4*)sC)[i] = src[i];
        if (threadIdx.x < 128) sN[threadIdx.x] = g_cn[ch * 128 + threadIdx.x];
        __syncthreads();
        for (int kk = 0; kk < 128; kk += 4) {
            const float4* c0 = (const float4*)(sC + (kk + 0) * 64);
            const float4* c1 = (const float4*)(sC + (kk + 1) * 64);
            const float4* c2 = (const float4*)(sC + (kk + 2) * 64);
            const float4* c3 = (const float4*)(sC + (kk + 3) * 64);
            float s0 = 0.f, s1 = 0.f, s2 = 0.f, s3 = 0.f;
            #pragma unroll
            for (int q = 0; q < 16; q++) {
                float4 a0 = c0[q], a1 = c1[q], a2 = c2[q], a3 = c3[q];
                float z0 = z[q*4+0], z1 = z[q*4+1], z2 = z[q*4+2], z3 = z[q*4+3];
                s0 = fmaf(z0, a0.x, s0); s0 = fmaf(z1, a0.y, s0);
                s0 = fmaf(z2, a0.z, s0); s0 = fmaf(z3, a0.w, s0);
                s1 = fmaf(z0, a1.x, s1); s1 = fmaf(z1, a1.y, s1);
                s1 = fmaf(z2, a1.z, s1); s1 = fmaf(z3, a1.w, s1);
                s2 = fmaf(z0, a2.x, s2); s2 = fmaf(z1, a2.y, s2);
                s2 = fmaf(z2, a2.z, s2); s2 = fmaf(z3, a2.w, s2);
                s3 = fmaf(z0, a3.x, s3); s3 = fmaf(z1, a3.y, s3);
                s3 = fmaf(z2, a3.z, s3); s3 = fmaf(z3, a3.w, s3);
            }
            float d0 = __fadd_rn(__fadd_rn(zz, -2.f * s0), sN[kk + 0]);
            float d1 = __fadd_rn(__fadd_rn(zz, -2.f * s1), sN[kk + 1]);
            float d2 = __fadd_rn(__fadd_rn(zz, -2.f * s2), sN[kk + 2]);
            float d3 = __fadd_rn(__fadd_rn(zz, -2.f * s3), sN[kk + 3]);
            if (d0 < best) { best = d0; bi = ch * 128 + kk + 0; }
            if (d1 < best) { best = d1; bi = ch * 128 + kk + 1; }
            if (d2 < best) { best = d2; bi = ch * 128 + kk + 2; }
            if (d3 < best) { best = d3; bi = ch * 128 + kk + 3; }
        }
    }
    g_idx[v] = bi;
}

// ---------------------------------------------------------------------------
// z_q scatter + straight-through: st[b][C][n] = fl(z + fl(cb[idx[n]][C] - z)).
// ---------------------------------------------------------------------------
__global__ __launch_bounds__(256) void zq_k(const float* __restrict__ cb) {
    int v = blockIdx.x * 256 + threadIdx.x;
    int b = v >> 12, n = v & 4095;
    int id = g_idx[v];
    const float* c = cb + (size_t)id * 64;
    size_t base = (size_t)b * 262144 + n;
    #pragma unroll 8
    for (int ch = 0; ch < 64; ch++) {
        size_t off = base + (size_t)ch * 4096;
        float zv = g_z[off];
        float q  = __ldg(c + ch);
        g_zq[off] = __fadd_rn(zv, __fadd_rn(q, -zv));
    }
}

// ---------------------------------------------------------------------------
// deconv1: zq_st[32,64,64,64] -> relu -> d1[32,128,128,128]
// parity-decomposed transposed conv; free rounding order (decoder only).
// ---------------------------------------------------------------------------
__global__ __launch_bounds__(256, 2) void deconv1_k(const float* __restrict__ bias) {
    __shared__ float sX[64 * 100];       // 10x10 patch per ci, all 64 ci
    __shared__ float sW[4 * 4 * 64 * 4]; // [p][ci4][co64][4]
    __shared__ float sB[64];
    int bz = blockIdx.z;
    int b = bz >> 1, half = bz & 1;
    int oht = blockIdx.y, owt = blockIdx.x;
    int t = threadIdx.x;
    if (t < 64) sB[t] = bias[half * 64 + t];
    int r0 = oht * 8 - 1, c0 = owt * 8 - 1;
    const float* zq = g_zq + (size_t)b * 262144;
    for (int i = t; i < 6400; i += 256) {
        int ci = i / 100, rr = (i % 100) / 10, cc = i % 10;
        int ih = r0 + rr, iw = c0 + cc;
        sX[i] = ((unsigned)ih < 64u && (unsigned)iw < 64u)
                ? zq[(size_t)ci * 4096 + ih * 64 + iw] : 0.f;
    }
    __syncthreads();
    int oh_l = t >> 4, ow_l = t & 15;
    int ph = oh_l & 1, pw = ow_l & 1, p = ph * 2 + pw;
    int xr = (oh_l >> 1) + ph;
    int xc = (ow_l >> 1) + pw;
    float acc[64];
    #pragma unroll
    for (int co = 0; co < 64; co++) acc[co] = sB[co];
    for (int cc4 = 0; cc4 < 16; cc4++) {
        __syncthreads();
        for (int i = t; i < 1024; i += 256) {
            int pp = i >> 8, rem = i & 255;
            int c4 = rem >> 6, co = rem & 63;
            ((float4*)sW)[i] =
                ((const float4*)g_wr1)[((size_t)pp * 64 + (cc4 * 4 + c4)) * 128 + half * 64 + co];
        }
        __syncthreads();
        #pragma unroll
        for (int c4 = 0; c4 < 4; c4++) {
            int base = (cc4 * 4 + c4) * 100;
            float x00 = sX[base + xr * 10 + xc];
            float x01 = sX[base + xr * 10 + xc + 1];
            float x10 = sX[base + (xr + 1) * 10 + xc];
            float x11 = sX[base + (xr + 1) * 10 + xc + 1];
            const float4* wrow = (const float4*)sW + (p * 4 + c4) * 64;
            #pragma unroll
            for (int co = 0; co < 64; co++) {
                float4 wv = wrow[co];
                float s = acc[co];
                s = fmaf(x00, wv.x, s);
                s = fmaf(x01, wv.y, s);
                s = fmaf(x10, wv.z, s);
                s = fmaf(x11, wv.w, s);
                acc[co] = s;
            }
        }
    }
    int oh = oht * 16 + oh_l, ow = owt * 16 + ow_l;
    size_t obase = (size_t)b * 2097152 + (size_t)(half * 64) * 16384
                 + (size_t)oh * 128 + ow;
    #pragma unroll
    for (int co = 0; co < 64; co++)
        g_d1[obase + (size_t)co * 16384] = fmaxf(acc[co], 0.f);
}

// ---------------------------------------------------------------------------
// deconv2: d1[32,128,128,128] -> out[32,3,256,256] (no relu), same structure.
// ---------------------------------------------------------------------------
__global__ __launch_bounds__(256) void deconv2_k(const float* __restrict__ bias,
                                                 float* __restrict__ out) {
    __shared__ float sX[32 * 100];
    __shared__ float sW[4 * 32 * 3 * 4];
    int b = blockIdx.z, oht = blockIdx.y, owt = blockIdx.x;
    int t = threadIdx.x;
    int r0 = oht * 8 - 1, c0 = owt * 8 - 1;
    int oh_l = t >> 4, ow_l = t & 15;
    int ph = oh_l & 1, pw = ow_l & 1, p = ph * 2 + pw;
    int xr = (oh_l >> 1) + ph;
    int xc = (ow_l >> 1) + pw;
    const float* d1b = g_d1 + (size_t)b * 2097152;
    float a0 = 0.f, a1 = 0.f, a2 = 0.f;
    for (int chn = 0; chn < 4; chn++) {
        __syncthreads();
        for (int i = t; i < 3200; i += 256) {
            int ci = i / 100, rr = (i % 100) / 10, cc = i % 10;
            int ih = r0 + rr, iw = c0 + cc;
            sX[i] = ((unsigned)ih < 128u && (unsigned)iw < 128u)
                    ? d1b[(size_t)(chn * 32 + ci) * 16384 + ih * 128 + iw] : 0.f;
        }
        for (int i = t; i < 384; i += 256) {
            int pp = i / 96, rem = i % 96;
            int ci = rem / 3, co = rem % 3;
            ((float4*)sW)[i] =
                ((const float4*)g_wr2)[((size_t)pp * 128 + chn * 32 + ci) * 3 + co];
        }
        __syncthreads();
        #pragma unroll 4
        for (int ci = 0; ci < 32; ci++) {
            int base = ci * 100;
            float x00 = sX[base + xr * 10 + xc];
            float x01 = sX[base + xr * 10 + xc + 1];
            float x10 = sX[base + (xr + 1) * 10 + xc];
            float x11 = sX[base + (xr + 1) * 10 + xc + 1];
            const float4* wr = (const float4*)sW + (p * 32 + ci) * 3;
            float4 w0 = wr[0], w1 = wr[1], w2 = wr[2];
            a0 = fmaf(x00, w0.x, a0); a0 = fmaf(x01, w0.y, a0);
            a0 = fmaf(x10, w0.z, a0); a0 = fmaf(x11, w0.w, a0);
            a1 = fmaf(x00, w1.x, a1); a1 = fmaf(x01, w1.y, a1);
            a1 = fmaf(x10, w1.z, a1); a1 = fmaf(x11, w1.w, a1);
            a2 = fmaf(x00, w2.x, a2); a2 = fmaf(x01, w2.y, a2);
            a2 = fmaf(x10, w2.z, a2); a2 = fmaf(x11, w2.w, a2);
        }
    }
    int oh = oht * 16 + oh_l, ow = owt * 16 + ow_l;
    size_t obase = (size_t)b * 3 * 65536 + (size_t)oh * 256 + ow;
    out[obase]              = a0 + __ldg(bias + 0);
    out[obase + 65536]      = a1 + __ldg(bias + 1);
    out[obase + 2 * 65536]  = a2 + __ldg(bias + 2);
}

// ---------------------------------------------------------------------------
extern "C" void kernel_launch(void* const* d_in, const int* in_sizes, int n_in,
                              void* d_out, int out_size) {
    const float* x      = (const float*)d_in[0];
    const float* enc_w1 = (const float*)d_in[1];
    const float* enc_b1 = (const float*)d_in[2];
    const float* enc_w2 = (const float*)d_in[3];
    const float* enc_b2 = (const float*)d_in[4];
    const float* dec_w1 = (const float*)d_in[5];
    const float* dec_b1 = (const float*)d_in[6];
    const float* dec_w2 = (const float*)d_in[7];
    const float* dec_b2 = (const float*)d_in[8];
    const float* cb     = (const float*)d_in[9];
    float* out = (float*)d_out;

    prep_k<<<64, 256>>>(cb, enc_w2, dec_w1, dec_w2);
    conv1_k<<<dim3(8, 8, BATCH), 256>>>(x, enc_w1, enc_b1);
    conv2_k<<<dim3(4, 8, BATCH), 256>>>(enc_b2);
    vq_k<<<512, 256>>>(cb);
    zq_k<<<512, 256>>>(cb);
    deconv1_k<<<dim3(8, 8, BATCH * 2), 256>>>(dec_b1);
    deconv2_k<<<dim3(16, 16, BATCH), 256>>>(dec_b2, out);
}

// round 5
// speedup vs baseline: 1.8360x; 1.2364x over previous
#include <cuda_runtime.h>
#include <cuda_bf16.h>

// ---------------------------------------------------------------------------
// VQVAE forward. Encoder + VQ replicate XLA-CPU (Eigen) fp32 rounding order
// bit-for-bit so the argmin matches the reference; decoder is free-order fp32.
// R5: packed f32x2 FMA (FFMA2) on conv2 / vq / deconv1 — each lane keeps the
// exact same sequential fmaf chain, so results are bit-identical. Shared-mem
// bank-conflict fixes in deconv1/deconv2 weight layouts.
// ---------------------------------------------------------------------------

#define BATCH 32
#define HID   128
#define EDIM  64
#define KCODES 512

typedef unsigned long long ull;

// scratch (device globals; no allocation allowed)
__device__ float g_h1[(size_t)BATCH * HID * 128 * 128];     // 268 MB
__device__ float g_z [(size_t)BATCH * EDIM * 64 * 64];      // 33.5 MB
__device__ float g_zq[(size_t)BATCH * EDIM * 64 * 64];      // 33.5 MB (z_q_st)
__device__ float g_d1[(size_t)BATCH * HID * 128 * 128];     // 268 MB
__device__ int   g_idx[BATCH * 4096];
__device__ float g_wT2[16 * 128 * 64];                      // conv2 w: [tap][ci][co]
__device__ float g_wr1[4 * 64 * 4 * 128];                   // dec_w1: [p][ci][tap][co]
__device__ float g_wr2[128 * 4 * 3 * 4];                    // dec_w2: [ci][p][co][tap4]
__device__ float g_cn[KCODES];                              // ||code||^2 (ref rounding)

// ---------------------------------------------------------------------------
// f32x2 helpers: two independent IEEE fp32 ops per instruction.
// ---------------------------------------------------------------------------
__device__ __forceinline__ unsigned smem_u32(const void* p) {
    unsigned a;
    asm("{ .reg .u64 t; cvta.to.shared.u64 t, %1; cvt.u32.u64 %0, t; }"
        : "=r"(a) : "l"(p));
    return a;
}
__device__ __forceinline__ ull pk2(float f) {
    ull d; unsigned u = __float_as_uint(f);
    asm("mov.b64 %0, {%1, %1};" : "=l"(d) : "r"(u));
    return d;
}
__device__ __forceinline__ ull pk2ab(float lo, float hi) {
    ull d;
    asm("mov.b64 %0, {%1, %2};" : "=l"(d)
        : "r"(__float_as_uint(lo)), "r"(__float_as_uint(hi)));
    return d;
}
__device__ __forceinline__ void fma2(ull& acc, ull a, ull b) {
    asm("fma.rn.f32x2 %0, %1, %2, %0;" : "+l"(acc) : "l"(a), "l"(b));
}
__device__ __forceinline__ void lds2(ull& a, ull& b, unsigned addr) {
    asm("ld.shared.v2.b64 {%0, %1}, [%2];" : "=l"(a), "=l"(b) : "r"(addr));
}
__device__ __forceinline__ void upk2(float& lo, float& hi, ull v) {
    unsigned l, h;
    asm("mov.b64 {%0, %1}, %2;" : "=r"(l), "=r"(h) : "l"(v));
    lo = __uint_as_float(l); hi = __uint_as_float(h);
}

// ---------------------------------------------------------------------------
// prep: codebook norms (separate mul+add sequential — XLA reduce), conv2 weight
// transpose [tap][ci][co], deconv weight rearrangement.
// ---------------------------------------------------------------------------
__global__ void prep_k(const float* __restrict__ cb,
                       const float* __restrict__ ew2,
                       const float* __restrict__ dw1,
                       const float* __restrict__ dw2) {
    int t = blockIdx.x * blockDim.x + threadIdx.x;
    int stride = gridDim.x * blockDim.x;
    if (t < KCODES) {
        float s = 0.f;
        for (int d = 0; d < EDIM; d++) {
            float v = cb[t * EDIM + d];
            s = __fadd_rn(s, __fmul_rn(v, v));
        }
        g_cn[t] = s;
    }
    // conv2 weights: g_wT2[tap*8192 + ci*64 + co] = ew2[co*2048 + ci*16 + tap]
    for (int e = t; e < 16 * 128 * 64; e += stride) {
        int tap = e >> 13;
        int ci  = (e >> 6) & 127;
        int co  = e & 63;
        g_wT2[e] = ew2[(size_t)co * 2048 + ci * 16 + tap];
    }
    // wr1: [p][ci][tap][co] : g_wr1[((p*64+ci)*4+tap)*128+co]
    //   tap j = jh*2+jw pairs with 2x2 input patch elem (jh,jw); src kernel
    //   element (ph+2jh, pw+2jw), p = ph*2+pw.
    for (int e = t; e < 4 * 64 * 4 * 128; e += stride) {
        int co  = e & 127;
        int tap = (e >> 7) & 3;
        int ci  = (e >> 9) & 63;
        int p   = e >> 15;
        int ph = p >> 1, pw = p & 1;
        int jh = tap >> 1, jw = tap & 1;
        g_wr1[e] = dw1[((size_t)co * 64 + ci) * 16 + (ph + 2 * jh) * 4 + (pw + 2 * jw)];
    }
    // wr2: [ci][p][co] with 4 taps per entry: g_wr2[((ci*4+p)*3+co)*4 + j]
    for (int e = t; e < 128 * 4 * 3; e += stride) {
        int ci  = e / 12;
        int rem = e % 12;
        int p   = rem / 3;
        int co  = rem % 3;
        int ph = p >> 1, pw = p & 1;
        const float* src = dw2 + ((size_t)co * 128 + ci) * 16;
        float* dst = g_wr2 + (size_t)e * 4;
        dst[0] = src[ ph      * 4 +  pw     ];
        dst[1] = src[ ph      * 4 + (pw + 2)];
        dst[2] = src[(ph + 2) * 4 +  pw     ];
        dst[3] = src[(ph + 2) * 4 + (pw + 2)];
    }
}

// ---------------------------------------------------------------------------
// conv1: x[32,3,256,256] -> relu -> h1[32,128,128,128], k=4 s=2 p=1.
// Sequential FMA chain, taps (kh,kw) row-major outer, ci fastest; bias after.
// ---------------------------------------------------------------------------
__global__ __launch_bounds__(256) void conv1_k(const float* __restrict__ x,
                                               const float* __restrict__ w,
                                               const float* __restrict__ bias) {
    __shared__ float sW2[128 * 48];   // [co][tap*3+ci]
    __shared__ float sX[3 * 34 * 34];
    int b = blockIdx.z, oht = blockIdx.y, owt = blockIdx.x;
    int t = threadIdx.x;
    for (int i = t; i < 6144; i += 256) {
        int co = i / 48, r = i - co * 48;
        int tap = r / 3, ci = r - tap * 3;
        sW2[i] = w[co * 48 + ci * 16 + tap];
    }
    int ih0 = oht * 32 - 1, iw0 = owt * 32 - 1;
    const float* xb = x + (size_t)b * 3 * 256 * 256;
    for (int i = t; i < 3 * 1156; i += 256) {
        int ci = i / 1156, r = (i % 1156) / 34, c = i % 34;
        int ih = ih0 + r, iw = iw0 + c;
        sX[i] = ((unsigned)ih < 256u && (unsigned)iw < 256u)
                ? xb[((size_t)ci * 256 + ih) * 256 + iw] : 0.f;
    }
    __syncthreads();
    int oh_l = t >> 4, ow_l = t & 15;
    float xw[48];
    #pragma unroll
    for (int kh = 0; kh < 4; kh++)
        #pragma unroll
        for (int kw = 0; kw < 4; kw++)
            #pragma unroll
            for (int ci = 0; ci < 3; ci++)
                xw[(kh * 4 + kw) * 3 + ci] =
                    sX[ci * 1156 + (2 * oh_l + kh) * 34 + (2 * ow_l + kw)];
    int oh = oht * 16 + oh_l, ow = owt * 16 + ow_l;
    size_t obase = (size_t)b * 2097152 + (size_t)oh * 128 + ow;
    #pragma unroll 4
    for (int co = 0; co < 128; co++) {
        float acc = 0.f;
        const float4* w4 = (const float4*)(sW2 + co * 48);
        #pragma unroll
        for (int q = 0; q < 12; q++) {
            float4 v = w4[q];
            acc = fmaf(xw[q * 4 + 0], v.x, acc);
            acc = fmaf(xw[q * 4 + 1], v.y, acc);
            acc = fmaf(xw[q * 4 + 2], v.z, acc);
            acc = fmaf(xw[q * 4 + 3], v.w, acc);
        }
        float val = __fadd_rn(acc, __ldg(bias + co));
        g_h1[obase + (size_t)co * 16384] = fmaxf(val, 0.f);
    }
}

// ---------------------------------------------------------------------------
// conv2 (FFMA2): h1 -> z[32,64,64,64]. Per-co chain UNCHANGED (taps row-major
// outer, ci inner); co packed in pairs into f32x2 lanes. x via __ldg, per-tap
// weights in smem. Thread = 2 horizontal outputs x 16 co.
// ---------------------------------------------------------------------------
__global__ __launch_bounds__(256) void conv2_k(const float* __restrict__ bias) {
    __shared__ __align__(16) float sW[8192];   // [ci][co] for current tap
    int b = blockIdx.z, oht = blockIdx.y, owt = blockIdx.x;   // grid (4, 8, B)
    int t = threadIdx.x;
    int tq = t & 3;
    int s  = t >> 2;
    int row = s >> 3;
    int cp  = s & 7;
    int oh  = oht * 8 + row;
    int ow0 = owt * 16 + cp * 2;
    const float* h1b = g_h1 + (size_t)b * 2097152;
    ull A[8], B[8];
    #pragma unroll
    for (int j = 0; j < 8; j++) { A[j] = 0ull; B[j] = 0ull; }
    unsigned swu = smem_u32(sW) + tq * 64;
    for (int tap = 0; tap < 16; tap++) {
        __syncthreads();
        {
            const float4* src = (const float4*)(g_wT2 + tap * 8192);
            float4* dst = (float4*)sW;
            #pragma unroll
            for (int i = 0; i < 8; i++) dst[t + 256 * i] = src[t + 256 * i];
        }
        __syncthreads();
        int kh = tap >> 2, kw = tap & 3;
        int ih  = 2 * oh + kh - 1;
        int iw0 = 2 * ow0 + kw - 1;
        bool p0 = ((unsigned)ih < 128u) && ((unsigned)iw0 < 128u);
        bool p1 = ((unsigned)ih < 128u) && ((unsigned)(iw0 + 2) < 128u);
        const float* xp = h1b + (size_t)ih * 128 + iw0;
        #pragma unroll 2
        for (int ci = 0; ci < 128; ci++) {
            float x0 = p0 ? __ldg(xp + (size_t)ci * 16384) : 0.f;
            float x1 = p1 ? __ldg(xp + (size_t)ci * 16384 + 2) : 0.f;
            ull X0 = pk2(x0), X1 = pk2(x1);
            unsigned a = swu + ci * 256;
            ull w0, w1, w2, w3, w4, w5, w6, w7;
            lds2(w0, w1, a);
            lds2(w2, w3, a + 16);
            lds2(w4, w5, a + 32);
            lds2(w6, w7, a + 48);
            fma2(A[0], X0, w0); fma2(A[1], X0, w1);
            fma2(A[2], X0, w2); fma2(A[3], X0, w3);
            fma2(A[4], X0, w4); fma2(A[5], X0, w5);
            fma2(A[6], X0, w6); fma2(A[7], X0, w7);
            fma2(B[0], X1, w0); fma2(B[1], X1, w1);
            fma2(B[2], X1, w2); fma2(B[3], X1, w3);
            fma2(B[4], X1, w4); fma2(B[5], X1, w5);
            fma2(B[6], X1, w6); fma2(B[7], X1, w7);
        }
    }
    size_t ob = (size_t)b * 262144 + (size_t)oh * 64 + ow0;
    #pragma unroll
    for (int j = 0; j < 8; j++) {
        int co0 = tq * 16 + 2 * j;
        float a_lo, a_hi, b_lo, b_hi;
        upk2(a_lo, a_hi, A[j]);
        upk2(b_lo, b_hi, B[j]);
        float bv0 = __ldg(bias + co0), bv1 = __ldg(bias + co0 + 1);
        g_z[ob + (size_t)co0 * 4096]           = __fadd_rn(a_lo, bv0);
        g_z[ob + (size_t)co0 * 4096 + 1]       = __fadd_rn(b_lo, bv0);
        g_z[ob + (size_t)(co0 + 1) * 4096]     = __fadd_rn(a_hi, bv1);
        g_z[ob + (size_t)(co0 + 1) * 4096 + 1] = __fadd_rn(b_hi, bv1);
    }
}

// ---------------------------------------------------------------------------
// VQ assign (FFMA2). Per-code chain preserved exactly: s over e ascending,
// d2 = fl(fl(zz - 2s) + cn), ascending scan, strict < (first min).
// Codes packed in pairs (interleaved layout in smem): lane0 = even code.
// ---------------------------------------------------------------------------
__global__ __launch_bounds__(256) void vq_k(const float* __restrict__ cb) {
    __shared__ __align__(16) float sC[128 * 64];  // [pair][e][2]
    __shared__ float sN[128];
    int v = blockIdx.x * 256 + threadIdx.x;
    float z[64];
    const float4* zp = (const float4*)(g_z + (size_t)v * 64);
    #pragma unroll
    for (int q = 0; q < 16; q++) {
        float4 f = zp[q];
        z[q * 4 + 0] = f.x; z[q * 4 + 1] = f.y;
        z[q * 4 + 2] = f.z; z[q * 4 + 3] = f.w;
    }
    float zz = 0.f;
    #pragma unroll
    for (int e = 0; e < 64; e++)
        zz = __fadd_rn(zz, __fmul_rn(z[e], z[e]));
    float best = 3.4e38f;
    int bi = 0;
    unsigned scu = smem_u32(sC);
    for (int ch = 0; ch < 4; ch++) {
        __syncthreads();
        const float* src = cb + (size_t)ch * 8192;
        for (int i = threadIdx.x; i < 8192; i += 256) {
            int pr = i >> 7, r = i & 127, e = r >> 1, s2 = r & 1;
            sC[i] = src[(2 * pr + s2) * 64 + e];
        }
        if (threadIdx.x < 128) sN[threadIdx.x] = g_cn[ch * 128 + threadIdx.x];
        __syncthreads();
        for (int kk = 0; kk < 128; kk += 16) {      // 8 pairs = 16 codes
            ull S[8];
            #pragma unroll
            for (int pp = 0; pp < 8; pp++) S[pp] = 0ull;
            unsigned base = scu + (kk >> 1) * 512;
            #pragma unroll
            for (int e = 0; e < 64; e += 2) {
                ull Z0 = pk2(z[e]), Z1 = pk2(z[e + 1]);
                #pragma unroll
                for (int pp = 0; pp < 8; pp++) {
                    ull w0, w1;
                    lds2(w0, w1, base + pp * 512 + e * 8);
                    fma2(S[pp], Z0, w0);
                    fma2(S[pp], Z1, w1);
                }
            }
            #pragma unroll
            for (int pp = 0; pp < 8; pp++) {
                float s0, s1;
                upk2(s0, s1, S[pp]);
                int k0 = kk + 2 * pp;
                float d0 = __fadd_rn(__fadd_rn(zz, -2.f * s0), sN[k0]);
                float d1 = __fadd_rn(__fadd_rn(zz, -2.f * s1), sN[k0 + 1]);
                if (d0 < best) { best = d0; bi = ch * 128 + k0; }
                if (d1 < best) { best = d1; bi = ch * 128 + k0 + 1; }
            }
        }
    }
    g_idx[v] = bi;
}

// ---------------------------------------------------------------------------
// z_q scatter + straight-through: st[b][C][n] = fl(z + fl(cb[idx[n]][C] - z)).
// ---------------------------------------------------------------------------
__global__ __launch_bounds__(256) void zq_k(const float* __restrict__ cb) {
    int v = blockIdx.x * 256 + threadIdx.x;
    int b = v >> 12, n = v & 4095;
    int id = g_idx[v];
    const float* c = cb + (size_t)id * 64;
    size_t base = (size_t)b * 262144 + n;
    #pragma unroll 8
    for (int ch = 0; ch < 64; ch++) {
        size_t off = base + (size_t)ch * 4096;
        float zv = g_z[off];
        float q  = __ldg(c + ch);
        g_zq[off] = __fadd_rn(zv, __fadd_rn(q, -zv));
    }
}

// ---------------------------------------------------------------------------
// deconv1 (FFMA2): zq_st[32,64,64,64] -> relu -> d1[32,128,128,128]
// Parity-decomposed transposed conv. Weights staged [p][c4][tap][co] with
// p-stride padded to 1028 floats (kills the 4-way p bank conflict). co packed
// in f32x2 pairs; x broadcast-packed once per tap.
// ---------------------------------------------------------------------------
__global__ __launch_bounds__(256, 2) void deconv1_k(const float* __restrict__ bias) {
    __shared__ float sX[64 * 100];                 // 10x10 patch per ci
    __shared__ __align__(16) float sW[4 * 1028];   // [p][(c4*4+tap)*16+co4] padded
    __shared__ float sB[64];
    int bz = blockIdx.z;
    int b = bz >> 1, half = bz & 1;
    int oht = blockIdx.y, owt = blockIdx.x;
    int t = threadIdx.x;
    if (t < 64) sB[t] = bias[half * 64 + t];
    int r0 = oht * 8 - 1, c0 = owt * 8 - 1;
    const float* zq = g_zq + (size_t)b * 262144;
    for (int i = t; i < 6400; i += 256) {
        int ci = i / 100, rr = (i % 100) / 10, cc = i % 10;
        int ih = r0 + rr, iw = c0 + cc;
        sX[i] = ((unsigned)ih < 64u && (unsigned)iw < 64u)
                ? zq[(size_t)ci * 4096 + ih * 64 + iw] : 0.f;
    }
    __syncthreads();
    int oh_l = t >> 4, ow_l = t & 15;
    int ph = oh_l & 1, pw = ow_l & 1, p = ph * 2 + pw;
    int xr = (oh_l >> 1) + ph;
    int xc = (ow_l >> 1) + pw;
    ull acc[32];
    #pragma unroll
    for (int j = 0; j < 32; j++) acc[j] = pk2ab(sB[2 * j], sB[2 * j + 1]);
    unsigned swu = smem_u32(sW) + p * 4112;        // p stride 1028 floats
    for (int cc4 = 0; cc4 < 16; cc4++) {
        __syncthreads();
        for (int i = t; i < 1024; i += 256) {
            int pp = i >> 8, rem = i & 255;        // rem = (c4*4+tap)*16 + co4
            int c4 = rem >> 6, tp = (rem >> 4) & 3, co4 = rem & 15;
            ((float4*)sW)[pp * 257 + rem] =
                ((const float4*)g_wr1)[((size_t)(pp * 64 + cc4 * 4 + c4) * 4 + tp) * 32
                                       + half * 16 + co4];
        }
        __syncthreads();
        #pragma unroll
        for (int c4 = 0; c4 < 4; c4++) {
            int base = (cc4 * 4 + c4) * 100;
            float xv0 = sX[base + xr * 10 + xc];
            float xv1 = sX[base + xr * 10 + xc + 1];
            float xv2 = sX[base + (xr + 1) * 10 + xc];
            float xv3 = sX[base + (xr + 1) * 10 + xc + 1];
            #pragma unroll
            for (int j = 0; j < 4; j++) {
                float xv = (j == 0) ? xv0 : (j == 1) ? xv1 : (j == 2) ? xv2 : xv3;
                ull X = pk2(xv);
                unsigned a = swu + ((c4 * 4 + j) * 64) * 4;
                #pragma unroll
                for (int k = 0; k < 16; k++) {
                    ull w0, w1;
                    lds2(w0, w1, a + k * 16);
                    fma2(acc[2 * k],     X, w0);
                    fma2(acc[2 * k + 1], X, w1);
                }
            }
        }
    }
    int oh = oht * 16 + oh_l, ow = owt * 16 + ow_l;
    size_t obase = (size_t)b * 2097152 + (size_t)(half * 64) * 16384
                 + (size_t)oh * 128 + ow;
    #pragma unroll
    for (int j = 0; j < 32; j++) {
        float lo, hi;
        upk2(lo, hi, acc[j]);
        g_d1[obase + (size_t)(2 * j) * 16384]     = fmaxf(lo, 0.f);
        g_d1[obase + (size_t)(2 * j + 1) * 16384] = fmaxf(hi, 0.f);
    }
}

// ---------------------------------------------------------------------------
// deconv2: d1[32,128,128,128] -> out[32,3,256,256]. Weight layout [ci][p][co]
// so parity groups hit distinct banks (conflict-free).
// ---------------------------------------------------------------------------
__global__ __launch_bounds__(256) void deconv2_k(const float* __restrict__ bias,
                                                 float* __restrict__ out) {
    __shared__ float sX[32 * 100];
    __shared__ __align__(16) float sW[32 * 4 * 3 * 4];   // [ci][p][co] float4-taps
    int b = blockIdx.z, oht = blockIdx.y, owt = blockIdx.x;
    int t = threadIdx.x;
    int r0 = oht * 8 - 1, c0 = owt * 8 - 1;
    int oh_l = t >> 4, ow_l = t & 15;
    int ph = oh_l & 1, pw = ow_l & 1, p = ph * 2 + pw;
    int xr = (oh_l >> 1) + ph;
    int xc = (ow_l >> 1) + pw;
    const float* d1b = g_d1 + (size_t)b * 2097152;
    float a0 = 0.f, a1 = 0.f, a2 = 0.f;
    for (int chn = 0; chn < 4; chn++) {
        __syncthreads();
        for (int i = t; i < 3200; i += 256) {
            int ci = i / 100, rr = (i % 100) / 10, cc = i % 10;
            int ih = r0 + rr, iw = c0 + cc;
            sX[i] = ((unsigned)ih < 128u && (unsigned)iw < 128u)
                    ? d1b[(size_t)(chn * 32 + ci) * 16384 + ih * 128 + iw] : 0.f;
        }
        for (int i = t; i < 384; i += 256) {
            int ci = i / 12, rem = i % 12;
            ((float4*)sW)[i] =
                ((const float4*)g_wr2)[(size_t)(chn * 32 + ci) * 12 + rem];
        }
        __syncthreads();
        #pragma unroll 4
        for (int ci = 0; ci < 32; ci++) {
            int base = ci * 100;
            float x00 = sX[base + xr * 10 + xc];
            float x01 = sX[base + xr * 10 + xc + 1];
            float x10 = sX[base + (xr + 1) * 10 + xc];
            float x11 = sX[base + (xr + 1) * 10 + xc + 1];
            const float4* wr = (const float4*)sW + (ci * 4 + p) * 3;
            float4 w0 = wr[0], w1 = wr[1], w2 = wr[2];
            a0 = fmaf(x00, w0.x, a0); a0 = fmaf(x01, w0.y, a0);
            a0 = fmaf(x10, w0.z, a0); a0 = fmaf(x11, w0.w, a0);
            a1 = fmaf(x00, w1.x, a1); a1 = fmaf(x01, w1.y, a1);
            a1 = fmaf(x10, w1.z, a1); a1 = fmaf(x11, w1.w, a1);
            a2 = fmaf(x00, w2.x, a2); a2 = fmaf(x01, w2.y, a2);
            a2 = fmaf(x10, w2.z, a2); a2 = fmaf(x11, w2.w, a2);
        }
    }
    int oh = oht * 16 + oh_l, ow = owt * 16 + ow_l;
    size_t obase = (size_t)b * 3 * 65536 + (size_t)oh * 256 + ow;
    out[obase]              = a0 + __ldg(bias + 0);
    out[obase + 65536]      = a1 + __ldg(bias + 1);
    out[obase + 2 * 65536]  = a2 + __ldg(bias + 2);
}

// ---------------------------------------------------------------------------
extern "C" void kernel_launch(void* const* d_in, const int* in_sizes, int n_in,
                              void* d_out, int out_size) {
    const float* x      = (const float*)d_in[0];
    const float* enc_w1 = (const float*)d_in[1];
    const float* enc_b1 = (const float*)d_in[2];
    const float* enc_w2 = (const float*)d_in[3];
    const float* enc_b2 = (const float*)d_in[4];
    const float* dec_w1 = (const float*)d_in[5];
    const float* dec_b1 = (const float*)d_in[6];
    const float* dec_w2 = (const float*)d_in[7];
    const float* dec_b2 = (const float*)d_in[8];
    const float* cb     = (const float*)d_in[9];
    float* out = (float*)d_out;

    prep_k<<<64, 256>>>(cb, enc_w2, dec_w1, dec_w2);
    conv1_k<<<dim3(8, 8, BATCH), 256>>>(x, enc_w1, enc_b1);
    conv2_k<<<dim3(4, 8, BATCH), 256>>>(enc_b2);
    vq_k<<<512, 256>>>(cb);
    zq_k<<<512, 256>>>(cb);
    deconv1_k<<<dim3(8, 8, BATCH * 2), 256>>>(dec_b1);
    deconv2_k<<<dim3(16, 16, BATCH), 256>>>(dec_b2, out);
}

// round 6
// speedup vs baseline: 2.0065x; 1.0929x over previous
#include <cuda_runtime.h>
#include <cuda_bf16.h>

// ---------------------------------------------------------------------------
// VQVAE forward. Encoder + VQ replicate XLA-CPU (Eigen) fp32 rounding order
// bit-for-bit so the argmin matches the reference; decoder is free-order fp32.
// R6: FFMA2 everywhere (conv1 co-pairs, deconv2 tap-lane split), vq processes
// 2 z-vectors/thread and absorbs the z_q scatter, deconv1 2 outputs/thread.
// ---------------------------------------------------------------------------

#define BATCH 32
#define HID   128
#define EDIM  64
#define KCODES 512

typedef unsigned long long ull;

// scratch (device globals; no allocation allowed)
__device__ float g_h1[(size_t)BATCH * HID * 128 * 128];     // 268 MB
__device__ float g_z [(size_t)BATCH * EDIM * 64 * 64];      // 33.5 MB
__device__ float g_zq[(size_t)BATCH * EDIM * 64 * 64];      // 33.5 MB (z_q_st)
__device__ float g_d1[(size_t)BATCH * HID * 128 * 128];     // 268 MB
__device__ float g_wT2[16 * 128 * 64];                      // conv2 w: [tap][ci][co]
__device__ float g_wr1[4 * 64 * 4 * 128];                   // dec_w1: [p][ci][tap][co]
__device__ float g_wr2[128 * 4 * 3 * 4];                    // dec_w2: [ci][p][co][tap4]
__device__ float g_cn[KCODES];                              // ||code||^2 (ref rounding)

// ---------------------------------------------------------------------------
// f32x2 helpers: two independent IEEE fp32 ops per instruction.
// ---------------------------------------------------------------------------
__device__ __forceinline__ unsigned smem_u32(const void* p) {
    unsigned a;
    asm("{ .reg .u64 t; cvta.to.shared.u64 t, %1; cvt.u32.u64 %0, t; }"
        : "=r"(a) : "l"(p));
    return a;
}
__device__ __forceinline__ ull pk2(float f) {
    ull d; unsigned u = __float_as_uint(f);
    asm("mov.b64 %0, {%1, %1};" : "=l"(d) : "r"(u));
    return d;
}
__device__ __forceinline__ ull pk2ab(float lo, float hi) {
    ull d;
    asm("mov.b64 %0, {%1, %2};" : "=l"(d)
        : "r"(__float_as_uint(lo)), "r"(__float_as_uint(hi)));
    return d;
}
__device__ __forceinline__ void fma2(ull& acc, ull a, ull b) {
    asm("fma.rn.f32x2 %0, %1, %2, %0;" : "+l"(acc) : "l"(a), "l"(b));
}
__device__ __forceinline__ void lds2(ull& a, ull& b, unsigned addr) {
    asm("ld.shared.v2.b64 {%0, %1}, [%2];" : "=l"(a), "=l"(b) : "r"(addr));
}
__device__ __forceinline__ void upk2(float& lo, float& hi, ull v) {
    unsigned l, h;
    asm("mov.b64 {%0, %1}, %2;" : "=r"(l), "=r"(h) : "l"(v));
    lo = __uint_as_float(l); hi = __uint_as_float(h);
}

// ---------------------------------------------------------------------------
// prep: codebook norms (separate mul+add sequential — XLA reduce), conv2 weight
// transpose [tap][ci][co], deconv weight rearrangement.
// ---------------------------------------------------------------------------
__global__ void prep_k(const float* __restrict__ cb,
                       const float* __restrict__ ew2,
                       const float* __restrict__ dw1,
                       const float* __restrict__ dw2) {
    int t = blockIdx.x * blockDim.x + threadIdx.x;
    int stride = gridDim.x * blockDim.x;
    if (t < KCODES) {
        float s = 0.f;
        for (int d = 0; d < EDIM; d++) {
            float v = cb[t * EDIM + d];
            s = __fadd_rn(s, __fmul_rn(v, v));
        }
        g_cn[t] = s;
    }
    for (int e = t; e < 16 * 128 * 64; e += stride) {
        int tap = e >> 13;
        int ci  = (e >> 6) & 127;
        int co  = e & 63;
        g_wT2[e] = ew2[(size_t)co * 2048 + ci * 16 + tap];
    }
    // wr1: [p][ci][tap][co]; tap j = jh*2+jw pairs with input patch elem (jh,jw),
    // src kernel element (ph+2jh, pw+2jw), p = ph*2+pw.
    for (int e = t; e < 4 * 64 * 4 * 128; e += stride) {
        int co  = e & 127;
        int tap = (e >> 7) & 3;
        int ci  = (e >> 9) & 63;
        int p   = e >> 15;
        int ph = p >> 1, pw = p & 1;
        int jh = tap >> 1, jw = tap & 1;
        g_wr1[e] = dw1[((size_t)co * 64 + ci) * 16 + (ph + 2 * jh) * 4 + (pw + 2 * jw)];
    }
    // wr2: [ci][p][co][tap4]
    for (int e = t; e < 128 * 4 * 3; e += stride) {
        int ci  = e / 12;
        int rem = e % 12;
        int p   = rem / 3;
        int co  = rem % 3;
        int ph = p >> 1, pw = p & 1;
        const float* src = dw2 + ((size_t)co * 128 + ci) * 16;
        float* dst = g_wr2 + (size_t)e * 4;
        dst[0] = src[ ph      * 4 +  pw     ];
        dst[1] = src[ ph      * 4 + (pw + 2)];
        dst[2] = src[(ph + 2) * 4 +  pw     ];
        dst[3] = src[(ph + 2) * 4 + (pw + 2)];
    }
}

// ---------------------------------------------------------------------------
// conv1 (FFMA2): x[32,3,256,256] -> relu -> h1[32,128,128,128], k=4 s=2 p=1.
// Per-co chain unchanged: k = tap*3+ci ascending, single fmaf chain, bias
// after. co packed in pairs; weights in smem as [k48][co128].
// ---------------------------------------------------------------------------
__global__ __launch_bounds__(256) void conv1_k(const float* __restrict__ x,
                                               const float* __restrict__ w,
                                               const float* __restrict__ bias) {
    __shared__ __align__(16) float sWT[48 * 128];   // [k][co]
    __shared__ float sX[3 * 34 * 34];
    int b = blockIdx.z, oht = blockIdx.y, owt = blockIdx.x;
    int t = threadIdx.x;
    for (int i = t; i < 6144; i += 256) {
        int k = i >> 7, co = i & 127;
        int tap = k / 3, ci = k - tap * 3;
        sWT[i] = w[co * 48 + ci * 16 + tap];
    }
    int ih0 = oht * 32 - 1, iw0 = owt * 32 - 1;
    const float* xb = x + (size_t)b * 3 * 256 * 256;
    for (int i = t; i < 3 * 1156; i += 256) {
        int ci = i / 1156, r = (i % 1156) / 34, c = i % 34;
        int ih = ih0 + r, iw = iw0 + c;
        sX[i] = ((unsigned)ih < 256u && (unsigned)iw < 256u)
                ? xb[((size_t)ci * 256 + ih) * 256 + iw] : 0.f;
    }
    __syncthreads();
    int oh_l = t >> 4, ow_l = t & 15;
    float xw[48];
    #pragma unroll
    for (int kh = 0; kh < 4; kh++)
        #pragma unroll
        for (int kw = 0; kw < 4; kw++)
            #pragma unroll
            for (int ci = 0; ci < 3; ci++)
                xw[(kh * 4 + kw) * 3 + ci] =
                    sX[ci * 1156 + (2 * oh_l + kh) * 34 + (2 * ow_l + kw)];
    int oh = oht * 16 + oh_l, ow = owt * 16 + ow_l;
    size_t obase = (size_t)b * 2097152 + (size_t)oh * 128 + ow;
    unsigned swt = smem_u32(sWT);
    #pragma unroll 2
    for (int g = 0; g < 8; g++) {          // 16 co per group
        ull acc[8];
        #pragma unroll
        for (int j = 0; j < 8; j++) acc[j] = 0ull;
        #pragma unroll
        for (int k = 0; k < 48; k++) {
            ull X = pk2(xw[k]);
            unsigned a = swt + k * 512 + g * 64;
            ull w0, w1, w2, w3, w4, w5, w6, w7;
            lds2(w0, w1, a);
            lds2(w2, w3, a + 16);
            lds2(w4, w5, a + 32);
            lds2(w6, w7, a + 48);
            fma2(acc[0], X, w0); fma2(acc[1], X, w1);
            fma2(acc[2], X, w2); fma2(acc[3], X, w3);
            fma2(acc[4], X, w4); fma2(acc[5], X, w5);
            fma2(acc[6], X, w6); fma2(acc[7], X, w7);
        }
        #pragma unroll
        for (int j = 0; j < 8; j++) {
            int co = g * 16 + 2 * j;
            float lo, hi;
            upk2(lo, hi, acc[j]);
            float v0 = __fadd_rn(lo, __ldg(bias + co));
            float v1 = __fadd_rn(hi, __ldg(bias + co + 1));
            g_h1[obase + (size_t)co * 16384]       = fmaxf(v0, 0.f);
            g_h1[obase + (size_t)(co + 1) * 16384] = fmaxf(v1, 0.f);
        }
    }
}

// ---------------------------------------------------------------------------
// conv2 (FFMA2): h1 -> z[32,64,64,64]. Per-co chain unchanged (taps row-major
// outer, ci inner). x via __ldg, per-tap weights in smem.
// ---------------------------------------------------------------------------
__global__ __launch_bounds__(256) void conv2_k(const float* __restrict__ bias) {
    __shared__ __align__(16) float sW[8192];   // [ci][co] for current tap
    int b = blockIdx.z, oht = blockIdx.y, owt = blockIdx.x;   // grid (4, 8, B)
    int t = threadIdx.x;
    int tq = t & 3;
    int s  = t >> 2;
    int row = s >> 3;
    int cp  = s & 7;
    int oh  = oht * 8 + row;
    int ow0 = owt * 16 + cp * 2;
    const float* h1b = g_h1 + (size_t)b * 2097152;
    ull A[8], B[8];
    #pragma unroll
    for (int j = 0; j < 8; j++) { A[j] = 0ull; B[j] = 0ull; }
    unsigned swu = smem_u32(sW) + tq * 64;
    for (int tap = 0; tap < 16; tap++) {
        __syncthreads();
        {
            const float4* src = (const float4*)(g_wT2 + tap * 8192);
            float4* dst = (float4*)sW;
            #pragma unroll
            for (int i = 0; i < 8; i++) dst[t + 256 * i] = src[t + 256 * i];
        }
        __syncthreads();
        int kh = tap >> 2, kw = tap & 3;
        int ih  = 2 * oh + kh - 1;
        int iw0 = 2 * ow0 + kw - 1;
        bool p0 = ((unsigned)ih < 128u) && ((unsigned)iw0 < 128u);
        bool p1 = ((unsigned)ih < 128u) && ((unsigned)(iw0 + 2) < 128u);
        const float* xp = h1b + (size_t)ih * 128 + iw0;
        #pragma unroll 2
        for (int ci = 0; ci < 128; ci++) {
            float x0 = p0 ? __ldg(xp + (size_t)ci * 16384) : 0.f;
            float x1 = p1 ? __ldg(xp + (size_t)ci * 16384 + 2) : 0.f;
            ull X0 = pk2(x0), X1 = pk2(x1);
            unsigned a = swu + ci * 256;
            ull w0, w1, w2, w3, w4, w5, w6, w7;
            lds2(w0, w1, a);
            lds2(w2, w3, a + 16);
            lds2(w4, w5, a + 32);
            lds2(w6, w7, a + 48);
            fma2(A[0], X0, w0); fma2(A[1], X0, w1);
            fma2(A[2], X0, w2); fma2(A[3], X0, w3);
            fma2(A[4], X0, w4); fma2(A[5], X0, w5);
            fma2(A[6], X0, w6); fma2(A[7], X0, w7);
            fma2(B[0], X1, w0); fma2(B[1], X1, w1);
            fma2(B[2], X1, w2); fma2(B[3], X1, w3);
            fma2(B[4], X1, w4); fma2(B[5], X1, w5);
            fma2(B[6], X1, w6); fma2(B[7], X1, w7);
        }
    }
    size_t ob = (size_t)b * 262144 + (size_t)oh * 64 + ow0;
    #pragma unroll
    for (int j = 0; j < 8; j++) {
        int co0 = tq * 16 + 2 * j;
        float a_lo, a_hi, b_lo, b_hi;
        upk2(a_lo, a_hi, A[j]);
        upk2(b_lo, b_hi, B[j]);
        float bv0 = __ldg(bias + co0), bv1 = __ldg(bias + co0 + 1);
        g_z[ob + (size_t)co0 * 4096]           = __fadd_rn(a_lo, bv0);
        g_z[ob + (size_t)co0 * 4096 + 1]       = __fadd_rn(b_lo, bv0);
        g_z[ob + (size_t)(co0 + 1) * 4096]     = __fadd_rn(a_hi, bv1);
        g_z[ob + (size_t)(co0 + 1) * 4096 + 1] = __fadd_rn(b_hi, bv1);
    }
}

// ---------------------------------------------------------------------------
// VQ assign + z_q scatter (FFMA2). Per-code chain preserved exactly; thread
// handles 2 z-vectors (u and u + 65536) sharing the codebook LDS stream, then
// writes z_q_st = fl(z + fl(q - z)) directly (z is already in registers).
// ---------------------------------------------------------------------------
__global__ __launch_bounds__(256) void vq_k(const float* __restrict__ cb) {
    __shared__ __align__(16) float sC[128 * 64];  // [pair][e][2]
    __shared__ float sN[128];
    int gid = blockIdx.x * 256 + threadIdx.x;
    int u0 = gid, u1 = gid + 65536;
    float zA[64], zB[64];
    {
        const float4* zp = (const float4*)(g_z + (size_t)u0 * 64);
        #pragma unroll
        for (int q = 0; q < 16; q++) {
            float4 f = zp[q];
            zA[q * 4 + 0] = f.x; zA[q * 4 + 1] = f.y;
            zA[q * 4 + 2] = f.z; zA[q * 4 + 3] = f.w;
        }
        const float4* zp2 = (const float4*)(g_z + (size_t)u1 * 64);
        #pragma unroll
        for (int q = 0; q < 16; q++) {
            float4 f = zp2[q];
            zB[q * 4 + 0] = f.x; zB[q * 4 + 1] = f.y;
            zB[q * 4 + 2] = f.z; zB[q * 4 + 3] = f.w;
        }
    }
    float zzA = 0.f, zzB = 0.f;
    #pragma unroll
    for (int e = 0; e < 64; e++) {
        zzA = __fadd_rn(zzA, __fmul_rn(zA[e], zA[e]));
        zzB = __fadd_rn(zzB, __fmul_rn(zB[e], zB[e]));
    }
    float bestA = 3.4e38f, bestB = 3.4e38f;
    int biA = 0, biB = 0;
    unsigned scu = smem_u32(sC);
    for (int ch = 0; ch < 4; ch++) {
        __syncthreads();
        const float* src = cb + (size_t)ch * 8192;
        for (int i = threadIdx.x; i < 8192; i += 256) {
            int pr = i >> 7, r = i & 127, e = r >> 1, s2 = r & 1;
            sC[i] = src[(2 * pr + s2) * 64 + e];
        }
        if (threadIdx.x < 128) sN[threadIdx.x] = g_cn[ch * 128 + threadIdx.x];
        __syncthreads();
        for (int kk = 0; kk < 128; kk += 16) {      // 8 pairs = 16 codes
            ull SA[8], SB[8];
            #pragma unroll
            for (int pp = 0; pp < 8; pp++) { SA[pp] = 0ull; SB[pp] = 0ull; }
            unsigned base = scu + (kk >> 1) * 512;
            #pragma unroll
            for (int e = 0; e < 64; e += 2) {
                ull ZA0 = pk2(zA[e]), ZA1 = pk2(zA[e + 1]);
                ull ZB0 = pk2(zB[e]), ZB1 = pk2(zB[e + 1]);
                #pragma unroll
                for (int pp = 0; pp < 8; pp++) {
                    ull w0, w1;
                    lds2(w0, w1, base + pp * 512 + e * 8);
                    fma2(SA[pp], ZA0, w0);
                    fma2(SA[pp], ZA1, w1);
                    fma2(SB[pp], ZB0, w0);
                    fma2(SB[pp], ZB1, w1);
                }
            }
            #pragma unroll
            for (int pp = 0; pp < 8; pp++) {
                int k0 = kk + 2 * pp;
                float n0 = sN[k0], n1 = sN[k0 + 1];
                float s0, s1;
                upk2(s0, s1, SA[pp]);
                float d0 = __fadd_rn(__fadd_rn(zzA, -2.f * s0), n0);
                float d1 = __fadd_rn(__fadd_rn(zzA, -2.f * s1), n1);
                if (d0 < bestA) { bestA = d0; biA = ch * 128 + k0; }
                if (d1 < bestA) { bestA = d1; biA = ch * 128 + k0 + 1; }
                upk2(s0, s1, SB[pp]);
                d0 = __fadd_rn(__fadd_rn(zzB, -2.f * s0), n0);
                d1 = __fadd_rn(__fadd_rn(zzB, -2.f * s1), n1);
                if (d0 < bestB) { bestB = d0; biB = ch * 128 + k0; }
                if (d1 < bestB) { bestB = d1; biB = ch * 128 + k0 + 1; }
            }
        }
    }
    // straight-through scatter
    {
        const float* c = cb + (size_t)biA * 64;
        size_t base = (size_t)(u0 >> 12) * 262144 + (u0 & 4095);
        #pragma unroll 8
        for (int e = 0; e < 64; e++) {
            float zv = zA[e];
            g_zq[base + (size_t)e * 4096] =
                __fadd_rn(zv, __fadd_rn(__ldg(c + e), -zv));
        }
        const float* c2 = cb + (size_t)biB * 64;
        size_t base2 = (size_t)(u1 >> 12) * 262144 + (u1 & 4095);
        #pragma unroll 8
        for (int e = 0; e < 64; e++) {
            float zv = zB[e];
            g_zq[base2 + (size_t)e * 4096] =
                __fadd_rn(zv, __fadd_rn(__ldg(c2 + e), -zv));
        }
    }
}

// ---------------------------------------------------------------------------
// deconv1 (FFMA2): zq_st[32,64,64,64] -> relu -> d1[32,128,128,128]
// Parity-decomposed transposed conv. Thread computes 2 outputs (ow, ow+16) of
// the same parity class, 32 co (co-pair packed). Weights staged per-4-ci with
// p-stride padded to 520 floats (conflict-free across p lanes).
// Block tile: 16(oh) x 32(ow); blockIdx.z = b*4 + coq (32 co per coq).
// ---------------------------------------------------------------------------
extern __shared__ float dsm1[];
__global__ __launch_bounds__(256, 2) void deconv1_k(const float* __restrict__ bias) {
    float* sX = dsm1;                 // [ci64][10][18] = 11520 floats
    float* sW = dsm1 + 11520;         // [p][(c4*4+tap)*32 + co] pad 520/p
    __shared__ float sB[32];
    int bz = blockIdx.z;
    int b = bz >> 2, coq = bz & 3;
    int oht = blockIdx.y, owt = blockIdx.x;
    int t = threadIdx.x;
    if (t < 32) sB[t] = bias[coq * 32 + t];
    int r0 = oht * 8 - 1, c0 = owt * 16 - 1;
    const float* zq = g_zq + (size_t)b * 262144;
    for (int i = t; i < 11520; i += 256) {
        int ci = i / 180, rem = i % 180;
        int rr = rem / 18, cc = rem % 18;
        int ih = r0 + rr, iw = c0 + cc;
        sX[i] = ((unsigned)ih < 64u && (unsigned)iw < 64u)
                ? zq[(size_t)ci * 4096 + ih * 64 + iw] : 0.f;
    }
    __syncthreads();
    int oh_l = t >> 4, ow_l = t & 15;
    int ph = oh_l & 1, pw = ow_l & 1, p = ph * 2 + pw;
    int xr = (oh_l >> 1) + ph;
    int xc = (ow_l >> 1) + pw;
    ull acc0[16], acc1[16];
    #pragma unroll
    for (int j = 0; j < 16; j++) {
        ull bv = pk2ab(sB[2 * j], sB[2 * j + 1]);
        acc0[j] = bv; acc1[j] = bv;
    }
    unsigned swu = smem_u32(sW) + p * 2080;        // p stride 520 floats
    for (int cc4 = 0; cc4 < 16; cc4++) {
        __syncthreads();
        for (int i = t; i < 512; i += 256) {       // 512 float4 = 2048 floats
            int pp = i >> 7, rem = i & 127;
            int c4 = rem >> 5, rem2 = rem & 31;
            int tap = rem2 >> 3, f4 = rem2 & 7;
            float4 v = ((const float4*)g_wr1)[
                (size_t)(((pp * 64 + cc4 * 4 + c4) * 4 + tap)) * 32 + coq * 8 + f4];
            *(float4*)(sW + pp * 520 + (c4 * 4 + tap) * 32 + f4 * 4) = v;
        }
        __syncthreads();
        #pragma unroll
        for (int c4 = 0; c4 < 4; c4++) {
            int xb = (cc4 * 4 + c4) * 180;
            #pragma unroll
            for (int tap = 0; tap < 4; tap++) {
                int xi = xb + (xr + (tap >> 1)) * 18 + xc + (tap & 1);
                ull X0 = pk2(sX[xi]);
                ull X1 = pk2(sX[xi + 8]);
                unsigned a = swu + (c4 * 4 + tap) * 128;
                #pragma unroll
                for (int j = 0; j < 8; j++) {
                    ull w0, w1;
                    lds2(w0, w1, a + j * 16);
                    fma2(acc0[2 * j],     X0, w0);
                    fma2(acc0[2 * j + 1], X0, w1);
                    fma2(acc1[2 * j],     X1, w0);
                    fma2(acc1[2 * j + 1], X1, w1);
                }
            }
        }
    }
    int oh = oht * 16 + oh_l, ow = owt * 32 + ow_l;
    size_t obase = (size_t)b * 2097152 + (size_t)(coq * 32) * 16384
                 + (size_t)oh * 128 + ow;
    #pragma unroll
    for (int j = 0; j < 16; j++) {
        float lo, hi;
        upk2(lo, hi, acc0[j]);
        g_d1[obase + (size_t)(2 * j) * 16384]     = fmaxf(lo, 0.f);
        g_d1[obase + (size_t)(2 * j + 1) * 16384] = fmaxf(hi, 0.f);
        upk2(lo, hi, acc1[j]);
        g_d1[obase + (size_t)(2 * j) * 16384 + 16]     = fmaxf(lo, 0.f);
        g_d1[obase + (size_t)(2 * j + 1) * 16384 + 16] = fmaxf(hi, 0.f);
    }
}

// ---------------------------------------------------------------------------
// deconv2 (FFMA2 tap-split): d1 -> out[32,3,256,256]. acc lanes = tap parities
// {0,2}/{1,3}, summed at the end (decoder rounding free).
// ---------------------------------------------------------------------------
__global__ __launch_bounds__(256) void deconv2_k(const float* __restrict__ bias,
                                                 float* __restrict__ out) {
    __shared__ float sX[32 * 100];
    __shared__ __align__(16) float sW[32 * 4 * 3 * 4];   // [ci][p][co][tap4]
    int b = blockIdx.z, oht = blockIdx.y, owt = blockIdx.x;
    int t = threadIdx.x;
    int r0 = oht * 8 - 1, c0 = owt * 8 - 1;
    int oh_l = t >> 4, ow_l = t & 15;
    int ph = oh_l & 1, pw = ow_l & 1, p = ph * 2 + pw;
    int xr = (oh_l >> 1) + ph;
    int xc = (ow_l >> 1) + pw;
    const float* d1b = g_d1 + (size_t)b * 2097152;
    ull a0 = 0ull, a1 = 0ull, a2 = 0ull;
    unsigned swu = smem_u32(sW) + p * 48;
    for (int chn = 0; chn < 4; chn++) {
        __syncthreads();
        for (int i = t; i < 3200; i += 256) {
            int ci = i / 100, rr = (i % 100) / 10, cc = i % 10;
            int ih = r0 + rr, iw = c0 + cc;
            sX[i] = ((unsigned)ih < 128u && (unsigned)iw < 128u)
                    ? d1b[(size_t)(chn * 32 + ci) * 16384 + ih * 128 + iw] : 0.f;
        }
        for (int i = t; i < 384; i += 256) {
            int ci = i / 12, rem = i % 12;
            ((float4*)sW)[i] =
                ((const float4*)g_wr2)[(size_t)(chn * 32 + ci) * 12 + rem];
        }
        __syncthreads();
        #pragma unroll 4
        for (int ci = 0; ci < 32; ci++) {
            int base = ci * 100;
            ull XA = pk2ab(sX[base + xr * 10 + xc], sX[base + xr * 10 + xc + 1]);
            ull XB = pk2ab(sX[base + (xr + 1) * 10 + xc],
                           sX[base + (xr + 1) * 10 + xc + 1]);
            unsigned a = swu + ci * 192;
            ull w01, w23, v01, v23, u01, u23;
            lds2(w01, w23, a);
            lds2(v01, v23, a + 16);
            lds2(u01, u23, a + 32);
            fma2(a0, XA, w01); fma2(a0, XB, w23);
            fma2(a1, XA, v01); fma2(a1, XB, v23);
            fma2(a2, XA, u01); fma2(a2, XB, u23);
        }
    }
    int oh = oht * 16 + oh_l, ow = owt * 16 + ow_l;
    size_t obase = (size_t)b * 3 * 65536 + (size_t)oh * 256 + ow;
    float lo, hi;
    upk2(lo, hi, a0); out[obase]             = (lo + hi) + __ldg(bias + 0);
    upk2(lo, hi, a1); out[obase + 65536]     = (lo + hi) + __ldg(bias + 1);
    upk2(lo, hi, a2); out[obase + 2 * 65536] = (lo + hi) + __ldg(bias + 2);
}

// ---------------------------------------------------------------------------
extern "C" void kernel_launch(void* const* d_in, const int* in_sizes, int n_in,
                              void* d_out, int out_size) {
    const float* x      = (const float*)d_in[0];
    const float* enc_w1 = (const float*)d_in[1];
    const float* enc_b1 = (const float*)d_in[2];
    const float* enc_w2 = (const float*)d_in[3];
    const float* enc_b2 = (const float*)d_in[4];
    const float* dec_w1 = (const float*)d_in[5];
    const float* dec_b1 = (const float*)d_in[6];
    const float* dec_w2 = (const float*)d_in[7];
    const float* dec_b2 = (const float*)d_in[8];
    const float* cb     = (const float*)d_in[9];
    float* out = (float*)d_out;

    cudaFuncSetAttribute(deconv1_k, cudaFuncAttributeMaxDynamicSharedMemorySize,
                         (11520 + 4 * 520) * 4);

    prep_k<<<64, 256>>>(cb, enc_w2, dec_w1, dec_w2);
    conv1_k<<<dim3(8, 8, BATCH), 256>>>(x, enc_w1, enc_b1);
    conv2_k<<<dim3(4, 8, BATCH), 256>>>(enc_b2);
    vq_k<<<256, 256>>>(cb);
    deconv1_k<<<dim3(4, 8, BATCH * 4), 256, (11520 + 4 * 520) * 4>>>(dec_b1);
    deconv2_k<<<dim3(16, 16, BATCH), 256>>>(dec_b2, out);
}

// round 7
// speedup vs baseline: 2.4434x; 1.2177x over previous
#include <cuda_runtime.h>
#include <cuda_bf16.h>

// ---------------------------------------------------------------------------
// VQVAE forward. Encoder + VQ replicate XLA-CPU (Eigen) fp32 rounding order
// bit-for-bit so the argmin matches the reference; decoder is free-order fp32.
// R7: conv2 4 outputs/thread (better FFMA2 slot mix); deconv1 8-ci weight
// staging (half the barriers). No arithmetic-order changes.
// ---------------------------------------------------------------------------

#define BATCH 32
#define HID   128
#define EDIM  64
#define KCODES 512

typedef unsigned long long ull;

// scratch (device globals; no allocation allowed)
__device__ float g_h1[(size_t)BATCH * HID * 128 * 128];     // 268 MB
__device__ float g_z [(size_t)BATCH * EDIM * 64 * 64];      // 33.5 MB
__device__ float g_zq[(size_t)BATCH * EDIM * 64 * 64];      // 33.5 MB (z_q_st)
__device__ float g_d1[(size_t)BATCH * HID * 128 * 128];     // 268 MB
__device__ float g_wT2[16 * 128 * 64];                      // conv2 w: [tap][ci][co]
__device__ float g_wr1[4 * 64 * 4 * 128];                   // dec_w1: [p][ci][tap][co]
__device__ float g_wr2[128 * 4 * 3 * 4];                    // dec_w2: [ci][p][co][tap4]
__device__ float g_cn[KCODES];                              // ||code||^2 (ref rounding)

// ---------------------------------------------------------------------------
// f32x2 helpers: two independent IEEE fp32 ops per instruction.
// ---------------------------------------------------------------------------
__device__ __forceinline__ unsigned smem_u32(const void* p) {
    unsigned a;
    asm("{ .reg .u64 t; cvta.to.shared.u64 t, %1; cvt.u32.u64 %0, t; }"
        : "=r"(a) : "l"(p));
    return a;
}
__device__ __forceinline__ ull pk2(float f) {
    ull d; unsigned u = __float_as_uint(f);
    asm("mov.b64 %0, {%1, %1};" : "=l"(d) : "r"(u));
    return d;
}
__device__ __forceinline__ ull pk2ab(float lo, float hi) {
    ull d;
    asm("mov.b64 %0, {%1, %2};" : "=l"(d)
        : "r"(__float_as_uint(lo)), "r"(__float_as_uint(hi)));
    return d;
}
__device__ __forceinline__ void fma2(ull& acc, ull a, ull b) {
    asm("fma.rn.f32x2 %0, %1, %2, %0;" : "+l"(acc) : "l"(a), "l"(b));
}
__device__ __forceinline__ void lds2(ull& a, ull& b, unsigned addr) {
    asm("ld.shared.v2.b64 {%0, %1}, [%2];" : "=l"(a), "=l"(b) : "r"(addr));
}
__device__ __forceinline__ void upk2(float& lo, float& hi, ull v) {
    unsigned l, h;
    asm("mov.b64 {%0, %1}, %2;" : "=r"(l), "=r"(h) : "l"(v));
    lo = __uint_as_float(l); hi = __uint_as_float(h);
}

// ---------------------------------------------------------------------------
// prep: codebook norms (separate mul+add sequential — XLA reduce), conv2 weight
// transpose [tap][ci][co], deconv weight rearrangement.
// ---------------------------------------------------------------------------
__global__ void prep_k(const float* __restrict__ cb,
                       const float* __restrict__ ew2,
                       const float* __restrict__ dw1,
                       const float* __restrict__ dw2) {
    int t = blockIdx.x * blockDim.x + threadIdx.x;
    int stride = gridDim.x * blockDim.x;
    if (t < KCODES) {
        float s = 0.f;
        for (int d = 0; d < EDIM; d++) {
            float v = cb[t * EDIM + d];
            s = __fadd_rn(s, __fmul_rn(v, v));
        }
        g_cn[t] = s;
    }
    for (int e = t; e < 16 * 128 * 64; e += stride) {
        int tap = e >> 13;
        int ci  = (e >> 6) & 127;
        int co  = e & 63;
        g_wT2[e] = ew2[(size_t)co * 2048 + ci * 16 + tap];
    }
    // wr1: [p][ci][tap][co]; tap j = jh*2+jw pairs with input patch elem (jh,jw),
    // src kernel element (ph+2jh, pw+2jw), p = ph*2+pw.
    for (int e = t; e < 4 * 64 * 4 * 128; e += stride) {
        int co  = e & 127;
        int tap = (e >> 7) & 3;
        int ci  = (e >> 9) & 63;
        int p   = e >> 15;
        int ph = p >> 1, pw = p & 1;
        int jh = tap >> 1, jw = tap & 1;
        g_wr1[e] = dw1[((size_t)co * 64 + ci) * 16 + (ph + 2 * jh) * 4 + (pw + 2 * jw)];
    }
    // wr2: [ci][p][co][tap4]
    for (int e = t; e < 128 * 4 * 3; e += stride) {
        int ci  = e / 12;
        int rem = e % 12;
        int p   = rem / 3;
        int co  = rem % 3;
        int ph = p >> 1, pw = p & 1;
        const float* src = dw2 + ((size_t)co * 128 + ci) * 16;
        float* dst = g_wr2 + (size_t)e * 4;
        dst[0] = src[ ph      * 4 +  pw     ];
        dst[1] = src[ ph      * 4 + (pw + 2)];
        dst[2] = src[(ph + 2) * 4 +  pw     ];
        dst[3] = src[(ph + 2) * 4 + (pw + 2)];
    }
}

// ---------------------------------------------------------------------------
// conv1 (FFMA2): x[32,3,256,256] -> relu -> h1[32,128,128,128], k=4 s=2 p=1.
// Per-co chain unchanged: k = tap*3+ci ascending, single fmaf chain, bias
// after. co packed in pairs; weights in smem as [k48][co128].
// ---------------------------------------------------------------------------
__global__ __launch_bounds__(256) void conv1_k(const float* __restrict__ x,
                                               const float* __restrict__ w,
                                               const float* __restrict__ bias) {
    __shared__ __align__(16) float sWT[48 * 128];   // [k][co]
    __shared__ float sX[3 * 34 * 34];
    int b = blockIdx.z, oht = blockIdx.y, owt = blockIdx.x;
    int t = threadIdx.x;
    for (int i = t; i < 6144; i += 256) {
        int k = i >> 7, co = i & 127;
        int tap = k / 3, ci = k - tap * 3;
        sWT[i] = w[co * 48 + ci * 16 + tap];
    }
    int ih0 = oht * 32 - 1, iw0 = owt * 32 - 1;
    const float* xb = x + (size_t)b * 3 * 256 * 256;
    for (int i = t; i < 3 * 1156; i += 256) {
        int ci = i / 1156, r = (i % 1156) / 34, c = i % 34;
        int ih = ih0 + r, iw = iw0 + c;
        sX[i] = ((unsigned)ih < 256u && (unsigned)iw < 256u)
                ? xb[((size_t)ci * 256 + ih) * 256 + iw] : 0.f;
    }
    __syncthreads();
    int oh_l = t >> 4, ow_l = t & 15;
    float xw[48];
    #pragma unroll
    for (int kh = 0; kh < 4; kh++)
        #pragma unroll
        for (int kw = 0; kw < 4; kw++)
            #pragma unroll
            for (int ci = 0; ci < 3; ci++)
                xw[(kh * 4 + kw) * 3 + ci] =
                    sX[ci * 1156 + (2 * oh_l + kh) * 34 + (2 * ow_l + kw)];
    int oh = oht * 16 + oh_l, ow = owt * 16 + ow_l;
    size_t obase = (size_t)b * 2097152 + (size_t)oh * 128 + ow;
    unsigned swt = smem_u32(sWT);
    #pragma unroll 2
    for (int g = 0; g < 8; g++) {          // 16 co per group
        ull acc[8];
        #pragma unroll
        for (int j = 0; j < 8; j++) acc[j] = 0ull;
        #pragma unroll
        for (int k = 0; k < 48; k++) {
            ull X = pk2(xw[k]);
            unsigned a = swt + k * 512 + g * 64;
            ull w0, w1, w2, w3, w4, w5, w6, w7;
            lds2(w0, w1, a);
            lds2(w2, w3, a + 16);
            lds2(w4, w5, a + 32);
            lds2(w6, w7, a + 48);
            fma2(acc[0], X, w0); fma2(acc[1], X, w1);
            fma2(acc[2], X, w2); fma2(acc[3], X, w3);
            fma2(acc[4], X, w4); fma2(acc[5], X, w5);
            fma2(acc[6], X, w6); fma2(acc[7], X, w7);
        }
        #pragma unroll
        for (int j = 0; j < 8; j++) {
            int co = g * 16 + 2 * j;
            float lo, hi;
            upk2(lo, hi, acc[j]);
            float v0 = __fadd_rn(lo, __ldg(bias + co));
            float v1 = __fadd_rn(hi, __ldg(bias + co + 1));
            g_h1[obase + (size_t)co * 16384]       = fmaxf(v0, 0.f);
            g_h1[obase + (size_t)(co + 1) * 16384] = fmaxf(v1, 0.f);
        }
    }
}

// ---------------------------------------------------------------------------
// conv2 (FFMA2, 4 outputs/thread): h1 -> z[32,64,64,64]. Per-co chain
// unchanged (taps row-major outer, ci inner). x via __ldg, per-tap weights in
// smem. Thread = 4 horizontal outputs x 16 co. Grid (2, 8, B).
// ---------------------------------------------------------------------------
__global__ __launch_bounds__(256) void conv2_k(const float* __restrict__ bias) {
    __shared__ __align__(16) float sW[8192];   // [ci][co] for current tap
    int b = blockIdx.z, oht = blockIdx.y, owt = blockIdx.x;
    int t = threadIdx.x;
    int tq = t & 3;
    int s  = t >> 2;
    int row = s >> 3;
    int cp  = s & 7;
    int oh  = oht * 8 + row;
    int ow0 = owt * 32 + cp * 4;
    const float* h1b = g_h1 + (size_t)b * 2097152;
    ull A0[8], A1[8], A2[8], A3[8];
    #pragma unroll
    for (int j = 0; j < 8; j++) { A0[j] = 0ull; A1[j] = 0ull; A2[j] = 0ull; A3[j] = 0ull; }
    unsigned swu = smem_u32(sW) + tq * 64;
    for (int tap = 0; tap < 16; tap++) {
        __syncthreads();
        {
            const float4* src = (const float4*)(g_wT2 + tap * 8192);
            float4* dst = (float4*)sW;
            #pragma unroll
            for (int i = 0; i < 8; i++) dst[t + 256 * i] = src[t + 256 * i];
        }
        __syncthreads();
        int kh = tap >> 2, kw = tap & 3;
        int ih  = 2 * oh + kh - 1;
        int iw0 = 2 * ow0 + kw - 1;
        bool hok = ((unsigned)ih < 128u);
        bool q0 = hok && ((unsigned)iw0 < 128u);
        bool q1 = hok && ((unsigned)(iw0 + 2) < 128u);
        bool q2 = hok && ((unsigned)(iw0 + 4) < 128u);
        bool q3 = hok && ((unsigned)(iw0 + 6) < 128u);
        const float* xp = h1b + (size_t)ih * 128 + iw0;
        #pragma unroll 2
        for (int ci = 0; ci < 128; ci++) {
            const float* xc = xp + (size_t)ci * 16384;
            float x0 = q0 ? __ldg(xc)     : 0.f;
            float x1 = q1 ? __ldg(xc + 2) : 0.f;
            float x2 = q2 ? __ldg(xc + 4) : 0.f;
            float x3 = q3 ? __ldg(xc + 6) : 0.f;
            ull X0 = pk2(x0), X1 = pk2(x1), X2 = pk2(x2), X3 = pk2(x3);
            unsigned a = swu + ci * 256;
            ull w0, w1, w2, w3, w4, w5, w6, w7;
            lds2(w0, w1, a);
            lds2(w2, w3, a + 16);
            lds2(w4, w5, a + 32);
            lds2(w6, w7, a + 48);
            fma2(A0[0], X0, w0); fma2(A0[1], X0, w1);
            fma2(A0[2], X0, w2); fma2(A0[3], X0, w3);
            fma2(A0[4], X0, w4); fma2(A0[5], X0, w5);
            fma2(A0[6], X0, w6); fma2(A0[7], X0, w7);
            fma2(A1[0], X1, w0); fma2(A1[1], X1, w1);
            fma2(A1[2], X1, w2); fma2(A1[3], X1, w3);
            fma2(A1[4], X1, w4); fma2(A1[5], X1, w5);
            fma2(A1[6], X1, w6); fma2(A1[7], X1, w7);
            fma2(A2[0], X2, w0); fma2(A2[1], X2, w1);
            fma2(A2[2], X2, w2); fma2(A2[3], X2, w3);
            fma2(A2[4], X2, w4); fma2(A2[5], X2, w5);
            fma2(A2[6], X2, w6); fma2(A2[7], X2, w7);
            fma2(A3[0], X3, w0); fma2(A3[1], X3, w1);
            fma2(A3[2], X3, w2); fma2(A3[3], X3, w3);
            fma2(A3[4], X3, w4); fma2(A3[5], X3, w5);
            fma2(A3[6], X3, w6); fma2(A3[7], X3, w7);
        }
    }
    size_t ob = (size_t)b * 262144 + (size_t)oh * 64 + ow0;
    #pragma unroll
    for (int j = 0; j < 8; j++) {
        int co0 = tq * 16 + 2 * j;
        float bv0 = __ldg(bias + co0), bv1 = __ldg(bias + co0 + 1);
        float lo, hi;
        size_t o0 = ob + (size_t)co0 * 4096;
        size_t o1 = ob + (size_t)(co0 + 1) * 4096;
        upk2(lo, hi, A0[j]); g_z[o0]     = __fadd_rn(lo, bv0); g_z[o1]     = __fadd_rn(hi, bv1);
        upk2(lo, hi, A1[j]); g_z[o0 + 1] = __fadd_rn(lo, bv0); g_z[o1 + 1] = __fadd_rn(hi, bv1);
        upk2(lo, hi, A2[j]); g_z[o0 + 2] = __fadd_rn(lo, bv0); g_z[o1 + 2] = __fadd_rn(hi, bv1);
        upk2(lo, hi, A3[j]); g_z[o0 + 3] = __fadd_rn(lo, bv0); g_z[o1 + 3] = __fadd_rn(hi, bv1);
    }
}

// ---------------------------------------------------------------------------
// VQ assign + z_q scatter (FFMA2). Per-code chain preserved exactly; thread
// handles 2 z-vectors sharing the codebook LDS stream, then writes
// z_q_st = fl(z + fl(q - z)) directly.
// ---------------------------------------------------------------------------
__global__ __launch_bounds__(256) void vq_k(const float* __restrict__ cb) {
    __shared__ __align__(16) float sC[128 * 64];  // [pair][e][2]
    __shared__ float sN[128];
    int gid = blockIdx.x * 256 + threadIdx.x;
    int u0 = gid, u1 = gid + 65536;
    float zA[64], zB[64];
    {
        const float4* zp = (const float4*)(g_z + (size_t)u0 * 64);
        #pragma unroll
        for (int q = 0; q < 16; q++) {
            float4 f = zp[q];
            zA[q * 4 + 0] = f.x; zA[q * 4 + 1] = f.y;
            zA[q * 4 + 2] = f.z; zA[q * 4 + 3] = f.w;
        }
        const float4* zp2 = (const float4*)(g_z + (size_t)u1 * 64);
        #pragma unroll
        for (int q = 0; q < 16; q++) {
            float4 f = zp2[q];
            zB[q * 4 + 0] = f.x; zB[q * 4 + 1] = f.y;
            zB[q * 4 + 2] = f.z; zB[q * 4 + 3] = f.w;
        }
    }
    float zzA = 0.f, zzB = 0.f;
    #pragma unroll
    for (int e = 0; e < 64; e++) {
        zzA = __fadd_rn(zzA, __fmul_rn(zA[e], zA[e]));
        zzB = __fadd_rn(zzB, __fmul_rn(zB[e], zB[e]));
    }
    float bestA = 3.4e38f, bestB = 3.4e38f;
    int biA = 0, biB = 0;
    unsigned scu = smem_u32(sC);
    for (int ch = 0; ch < 4; ch++) {
        __syncthreads();
        const float* src = cb + (size_t)ch * 8192;
        for (int i = threadIdx.x; i < 8192; i += 256) {
            int pr = i >> 7, r = i & 127, e = r >> 1, s2 = r & 1;
            sC[i] = src[(2 * pr + s2) * 64 + e];
        }
        if (threadIdx.x < 128) sN[threadIdx.x] = g_cn[ch * 128 + threadIdx.x];
        __syncthreads();
        for (int kk = 0; kk < 128; kk += 16) {      // 8 pairs = 16 codes
            ull SA[8], SB[8];
            #pragma unroll
            for (int pp = 0; pp < 8; pp++) { SA[pp] = 0ull; SB[pp] = 0ull; }
            unsigned base = scu + (kk >> 1) * 512;
            #pragma unroll
            for (int e = 0; e < 64; e += 2) {
                ull ZA0 = pk2(zA[e]), ZA1 = pk2(zA[e + 1]);
                ull ZB0 = pk2(zB[e]), ZB1 = pk2(zB[e + 1]);
                #pragma unroll
                for (int pp = 0; pp < 8; pp++) {
                    ull w0, w1;
                    lds2(w0, w1, base + pp * 512 + e * 8);
                    fma2(SA[pp], ZA0, w0);
                    fma2(SA[pp], ZA1, w1);
                    fma2(SB[pp], ZB0, w0);
                    fma2(SB[pp], ZB1, w1);
                }
            }
            #pragma unroll
            for (int pp = 0; pp < 8; pp++) {
                int k0 = kk + 2 * pp;
                float n0 = sN[k0], n1 = sN[k0 + 1];
                float s0, s1;
                upk2(s0, s1, SA[pp]);
                float d0 = __fadd_rn(__fadd_rn(zzA, -2.f * s0), n0);
                float d1 = __fadd_rn(__fadd_rn(zzA, -2.f * s1), n1);
                if (d0 < bestA) { bestA = d0; biA = ch * 128 + k0; }
                if (d1 < bestA) { bestA = d1; biA = ch * 128 + k0 + 1; }
                upk2(s0, s1, SB[pp]);
                d0 = __fadd_rn(__fadd_rn(zzB, -2.f * s0), n0);
                d1 = __fadd_rn(__fadd_rn(zzB, -2.f * s1), n1);
                if (d0 < bestB) { bestB = d0; biB = ch * 128 + k0; }
                if (d1 < bestB) { bestB = d1; biB = ch * 128 + k0 + 1; }
            }
        }
    }
    {
        const float* c = cb + (size_t)biA * 64;
        size_t base = (size_t)(u0 >> 12) * 262144 + (u0 & 4095);
        #pragma unroll 8
        for (int e = 0; e < 64; e++) {
            float zv = zA[e];
            g_zq[base + (size_t)e * 4096] =
                __fadd_rn(zv, __fadd_rn(__ldg(c + e), -zv));
        }
        const float* c2 = cb + (size_t)biB * 64;
        size_t base2 = (size_t)(u1 >> 12) * 262144 + (u1 & 4095);
        #pragma unroll 8
        for (int e = 0; e < 64; e++) {
            float zv = zB[e];
            g_zq[base2 + (size_t)e * 4096] =
                __fadd_rn(zv, __fadd_rn(__ldg(c2 + e), -zv));
        }
    }
}

// ---------------------------------------------------------------------------
// deconv1 (FFMA2): zq_st -> relu -> d1. Parity-decomposed; thread = 2 outputs
// (ow, ow+16) x 32 co (pair-packed). Weights staged 8 ci per sync, p-stride
// padded to 1032 floats (p lanes at distinct bank offsets 0/8/16/24).
// ---------------------------------------------------------------------------
extern __shared__ float dsm1[];
__global__ __launch_bounds__(256, 2) void deconv1_k(const float* __restrict__ bias) {
    float* sX = dsm1;                 // [ci64][10][18] = 11520 floats
    float* sW = dsm1 + 11520;         // [p][(c8*4+tap)*32 + co], stride 1032/p
    __shared__ float sB[32];
    int bz = blockIdx.z;
    int b = bz >> 2, coq = bz & 3;
    int oht = blockIdx.y, owt = blockIdx.x;
    int t = threadIdx.x;
    if (t < 32) sB[t] = bias[coq * 32 + t];
    int r0 = oht * 8 - 1, c0 = owt * 16 - 1;
    const float* zq = g_zq + (size_t)b * 262144;
    for (int i = t; i < 11520; i += 256) {
        int ci = i / 180, rem = i % 180;
        int rr = rem / 18, cc = rem % 18;
        int ih = r0 + rr, iw = c0 + cc;
        sX[i] = ((unsigned)ih < 64u && (unsigned)iw < 64u)
                ? zq[(size_t)ci * 4096 + ih * 64 + iw] : 0.f;
    }
    __syncthreads();
    int oh_l = t >> 4, ow_l = t & 15;
    int ph = oh_l & 1, pw = ow_l & 1, p = ph * 2 + pw;
    int xr = (oh_l >> 1) + ph;
    int xc = (ow_l >> 1) + pw;
    ull acc0[16], acc1[16];
    #pragma unroll
    for (int j = 0; j < 16; j++) {
        ull bv = pk2ab(sB[2 * j], sB[2 * j + 1]);
        acc0[j] = bv; acc1[j] = bv;
    }
    unsigned swu = smem_u32(sW) + p * 4128;        // p stride 1032 floats
    for (int cc8 = 0; cc8 < 8; cc8++) {
        __syncthreads();
        for (int i = t; i < 1024; i += 256) {      // 1024 float4 = 4096 floats
            int pp = i >> 8, rem = i & 255;
            int c8 = rem >> 5, rem2 = rem & 31;
            int tap = rem2 >> 3, f4 = rem2 & 7;
            float4 v = ((const float4*)g_wr1)[
                (size_t)(((pp * 64 + cc8 * 8 + c8) * 4 + tap)) * 32 + coq * 8 + f4];
            *(float4*)(sW + pp * 1032 + (c8 * 4 + tap) * 32 + f4 * 4) = v;
        }
        __syncthreads();
        #pragma unroll
        for (int c8 = 0; c8 < 8; c8++) {
            int xb = (cc8 * 8 + c8) * 180;
            #pragma unroll
            for (int tap = 0; tap < 4; tap++) {
                int xi = xb + (xr + (tap >> 1)) * 18 + xc + (tap & 1);
                ull X0 = pk2(sX[xi]);
                ull X1 = pk2(sX[xi + 8]);
                unsigned a = swu + (c8 * 4 + tap) * 128;
                #pragma unroll
                for (int j = 0; j < 8; j++) {
                    ull w0, w1;
                    lds2(w0, w1, a + j * 16);
                    fma2(acc0[2 * j],     X0, w0);
                    fma2(acc0[2 * j + 1], X0, w1);
                    fma2(acc1[2 * j],     X1, w0);
                    fma2(acc1[2 * j + 1], X1, w1);
                }
            }
        }
    }
    int oh = oht * 16 + oh_l, ow = owt * 32 + ow_l;
    size_t obase = (size_t)b * 2097152 + (size_t)(coq * 32) * 16384
                 + (size_t)oh * 128 + ow;
    #pragma unroll
    for (int j = 0; j < 16; j++) {
        float lo, hi;
        upk2(lo, hi, acc0[j]);
        g_d1[obase + (size_t)(2 * j) * 16384]     = fmaxf(lo, 0.f);
        g_d1[obase + (size_t)(2 * j + 1) * 16384] = fmaxf(hi, 0.f);
        upk2(lo, hi, acc1[j]);
        g_d1[obase + (size_t)(2 * j) * 16384 + 16]     = fmaxf(lo, 0.f);
        g_d1[obase + (size_t)(2 * j + 1) * 16384 + 16] = fmaxf(hi, 0.f);
    }
}

// ---------------------------------------------------------------------------
// deconv2 (FFMA2 tap-split): d1 -> out[32,3,256,256]. acc lanes = tap parities
// {0,2}/{1,3}, summed at the end (decoder rounding free).
// ---------------------------------------------------------------------------
__global__ __launch_bounds__(256) void deconv2_k(const float* __restrict__ bias,
                                                 float* __restrict__ out) {
    __shared__ float sX[32 * 100];
    __shared__ __align__(16) float sW[32 * 4 * 3 * 4];   // [ci][p][co][tap4]
    int b = blockIdx.z, oht = blockIdx.y, owt = blockIdx.x;
    int t = threadIdx.x;
    int r0 = oht * 8 - 1, c0 = owt * 8 - 1;
    int oh_l = t >> 4, ow_l = t & 15;
    int ph = oh_l & 1, pw = ow_l & 1, p = ph * 2 + pw;
    int xr = (oh_l >> 1) + ph;
    int xc = (ow_l >> 1) + pw;
    const float* d1b = g_d1 + (size_t)b * 2097152;
    ull a0 = 0ull, a1 = 0ull, a2 = 0ull;
    unsigned swu = smem_u32(sW) + p * 48;
    for (int chn = 0; chn < 4; chn++) {
        __syncthreads();
        for (int i = t; i < 3200; i += 256) {
            int ci = i / 100, rr = (i % 100) / 10, cc = i % 10;
            int ih = r0 + rr, iw = c0 + cc;
            sX[i] = ((unsigned)ih < 128u && (unsigned)iw < 128u)
                    ? d1b[(size_t)(chn * 32 + ci) * 16384 + ih * 128 + iw] : 0.f;
        }
        for (int i = t; i < 384; i += 256) {
            int ci = i / 12, rem = i % 12;
            ((float4*)sW)[i] =
                ((const float4*)g_wr2)[(size_t)(chn * 32 + ci) * 12 + rem];
        }
        __syncthreads();
        #pragma unroll 4
        for (int ci = 0; ci < 32; ci++) {
            int base = ci * 100;
            ull XA = pk2ab(sX[base + xr * 10 + xc], sX[base + xr * 10 + xc + 1]);
            ull XB = pk2ab(sX[base + (xr + 1) * 10 + xc],
                           sX[base + (xr + 1) * 10 + xc + 1]);
            unsigned a = swu + ci * 192;
            ull w01, w23, v01, v23, u01, u23;
            lds2(w01, w23, a);
            lds2(v01, v23, a + 16);
            lds2(u01, u23, a + 32);
            fma2(a0, XA, w01); fma2(a0, XB, w23);
            fma2(a1, XA, v01); fma2(a1, XB, v23);
            fma2(a2, XA, u01); fma2(a2, XB, u23);
        }
    }
    int oh = oht * 16 + oh_l, ow = owt * 16 + ow_l;
    size_t obase = (size_t)b * 3 * 65536 + (size_t)oh * 256 + ow;
    float lo, hi;
    upk2(lo, hi, a0); out[obase]             = (lo + hi) + __ldg(bias + 0);
    upk2(lo, hi, a1); out[obase + 65536]     = (lo + hi) + __ldg(bias + 1);
    upk2(lo, hi, a2); out[obase + 2 * 65536] = (lo + hi) + __ldg(bias + 2);
}

// ---------------------------------------------------------------------------
extern "C" void kernel_launch(void* const* d_in, const int* in_sizes, int n_in,
                              void* d_out, int out_size) {
    const float* x      = (const float*)d_in[0];
    const float* enc_w1 = (const float*)d_in[1];
    const float* enc_b1 = (const float*)d_in[2];
    const float* enc_w2 = (const float*)d_in[3];
    const float* enc_b2 = (const float*)d_in[4];
    const float* dec_w1 = (const float*)d_in[5];
    const float* dec_b1 = (const float*)d_in[6];
    const float* dec_w2 = (const float*)d_in[7];
    const float* dec_b2 = (const float*)d_in[8];
    const float* cb     = (const float*)d_in[9];
    float* out = (float*)d_out;

    cudaFuncSetAttribute(deconv1_k, cudaFuncAttributeMaxDynamicSharedMemorySize,
                         (11520 + 4 * 1032) * 4);

    prep_k<<<64, 256>>>(cb, enc_w2, dec_w1, dec_w2);
    conv1_k<<<dim3(8, 8, BATCH), 256>>>(x, enc_w1, enc_b1);
    conv2_k<<<dim3(2, 8, BATCH), 256>>>(enc_b2);
    vq_k<<<256, 256>>>(cb);
    deconv1_k<<<dim3(4, 8, BATCH * 4), 256, (11520 + 4 * 1032) * 4>>>(dec_b1);
    deconv2_k<<<dim3(16, 16, BATCH), 256>>>(dec_b2, out);
}